// round 14
// baseline (speedup 1.0000x reference)
#include <cuda_runtime.h>
#include <cuda_fp16.h>
#include <math.h>
#include <cstdint>

#define NN   50000
#define EE   150000
#define GG   200
#define DD   320
#define EDIN 15
#define EHH  32
#define NBB  3
#define NTT  9
#define NE9  (NTT * EE)
#define NT9  (NN * NTT)
#define NND_C ((size_t)NN * DD)

// ---------------- scratch (static device globals; allocation-free) ----------------
__device__ __half g_NEAH[NTT * EE * EHH];
__device__ float  g_XSD[NN * 64];              // packed [node][0:32]=XS, [32:64]=XD
__device__ __half g_QKVH[3 * NTT * NN * DD];   // [qkv][t][N][D]
__device__ float  g_QW[NTT * NN * 64];
__device__ __half g_WNEAH[NN * NTT * EHH];
__device__ float  g_ACC[NN * DD];
__device__ float  g_H[NN * DD];
__device__ __half g_HH[NN * DD];
// fp16 pre-transposed weights, B-operand layout [Nout][K] (K contiguous)
__device__ __half g_WQKVTH[NBB * 3 * NTT * DD * DD];  // [b][qkv][t][n][k]
__device__ float  g_BQKV[NBB * 3 * NTT * DD];
__device__ __half g_WSUMTH[NBB * DD * DD];
__device__ float  g_BSUM[NBB * DD];
__device__ __half g_WERTH[NBB * DD * (NTT * EHH)];  // [b][320][288]
__device__ __half g_WQWBH[NBB * NTT * 64 * DD];     // [bt][64][320], rows 32..63 zero
__device__ __half g_W1TH[64 * DD];                  // rows 0-31: W1src^T, 32-63: W1dst^T
// CSR keyed by (node, type)
__device__ int   g_CNT2[NT9 + 1];
__device__ int   g_POS2[NT9];
__device__ int   g_CSRE[NE9];                  // pe = t*EE + e (for NEA)
__device__ int   g_CSRS[NE9];                  // src node
__device__ float g_GS[GG];
__device__ float g_GQ[GG];
__device__ int   g_GC[GG];
__device__ float g_MEAN[GG];
__device__ float g_RSTD[GG];
__device__ unsigned g_OUTU[GG * DD];

// ---------------- helpers ----------------
__device__ __forceinline__ uint32_t smem_u32(const void* p)
{
    uint32_t a;
    asm("{ .reg .u64 t; cvta.to.shared.u64 t, %1; cvt.u32.u64 %0, t; }" : "=r"(a) : "l"(p));
    return a;
}

__device__ __forceinline__ void cp16(unsigned dst, const void* src, bool p)
{
    asm volatile("cp.async.cg.shared.global [%0], [%1], 16, %2;"
                 :: "r"(dst), "l"(src), "r"(p ? 16 : 0));
}
__device__ __forceinline__ void cp_commit() { asm volatile("cp.async.commit_group;"); }
template<int N> __device__ __forceinline__ void cp_wait() { asm volatile("cp.async.wait_group %0;" :: "n"(N)); }

// ---------------- FP16 tensor-core GEMM (m16n8k16), cp.async double-buffered ----------
template<bool ACCUM, bool WRITEF, bool WRITEH>
__global__ void __launch_bounds__(256) hgemm(
    const __half* __restrict__ A, const __half* __restrict__ B,
    const float* __restrict__ bias, float* __restrict__ C, __half* __restrict__ CH,
    int M, int K, int Nout,
    long aZ, long bZ, long cZ, long biasZ)
{
    __shared__ __align__(16) __half As[2][128 * 40];
    __shared__ __align__(16) __half Bs[2][64 * 40];

    const int z = blockIdx.z;
    A += (size_t)z * aZ; B += (size_t)z * bZ;
    if (WRITEF || ACCUM) C += (size_t)z * cZ;
    if (WRITEH) CH += (size_t)z * cZ;
    if (bias) bias += (size_t)z * biasZ;

    const int tid  = threadIdx.x;
    const int lane = tid & 31;
    const int wid  = tid >> 5;
    const int wm   = (wid & 3) * 32;
    const int wn   = (wid >> 2) * 32;
    const int m0 = blockIdx.y * 128;
    const int n0 = blockIdx.x * 64;

    uint32_t uA[2] = { smem_u32(As[0]), smem_u32(As[1]) };
    uint32_t uB[2] = { smem_u32(Bs[0]), smem_u32(Bs[1]) };

    const int arow = tid >> 2;
    const int acol = (tid & 3) * 8;

    float acc[2][4][4];
#pragma unroll
    for (int mt = 0; mt < 2; mt++)
#pragma unroll
        for (int nt = 0; nt < 4; nt++)
#pragma unroll
            for (int i = 0; i < 4; i++) acc[mt][nt][i] = 0.f;

    const int nk = K / 32;

#define LOADC(c, buf) do {                                                                   \
    int k0_ = (c) * 32;                                                                      \
    int r0_ = m0 + arow;                                                                     \
    cp16(uA[buf] + (unsigned)(arow * 40 + acol) * 2,                                         \
         A + (size_t)r0_ * K + k0_ + acol, r0_ < M);                                         \
    cp16(uA[buf] + (unsigned)((arow + 64) * 40 + acol) * 2,                                  \
         A + (size_t)(r0_ + 64) * K + k0_ + acol, (r0_ + 64) < M);                           \
    cp16(uB[buf] + (unsigned)(arow * 40 + acol) * 2,                                         \
         B + (size_t)(n0 + arow) * K + k0_ + acol, true);                                    \
} while (0)

    LOADC(0, 0);
    cp_commit();

    for (int kt = 0; kt < nk; kt++) {
        int s = kt & 1, o = s ^ 1;
        if (kt + 1 < nk) {
            LOADC(kt + 1, o);
            cp_commit();
            cp_wait<1>();
        } else {
            cp_wait<0>();
        }
        __syncthreads();

        uint32_t uAb = uA[s], uBb = uB[s];
#pragma unroll
        for (int ks = 0; ks < 32; ks += 16) {
            uint32_t af[2][4], bf[4][2];
#pragma unroll
            for (int mt = 0; mt < 2; mt++) {
                int row = wm + mt * 16 + (lane & 15);
                int col = ks + ((lane >> 4) << 3);
                uint32_t addr = uAb + (unsigned)(row * 40 + col) * 2;
                asm volatile("ldmatrix.sync.aligned.m8n8.x4.shared.b16 {%0,%1,%2,%3}, [%4];"
                             : "=r"(af[mt][0]), "=r"(af[mt][1]), "=r"(af[mt][2]), "=r"(af[mt][3])
                             : "r"(addr));
            }
#pragma unroll
            for (int nt = 0; nt < 4; nt++) {
                int row = wn + nt * 8 + (lane & 7);
                int col = ks + (((lane >> 3) & 1) << 3);
                uint32_t addr = uBb + (unsigned)(row * 40 + col) * 2;
                asm volatile("ldmatrix.sync.aligned.m8n8.x2.shared.b16 {%0,%1}, [%2];"
                             : "=r"(bf[nt][0]), "=r"(bf[nt][1]) : "r"(addr));
            }
#pragma unroll
            for (int nt = 0; nt < 4; nt++)
#pragma unroll
                for (int mt = 0; mt < 2; mt++)
                    asm volatile(
                        "mma.sync.aligned.m16n8k16.row.col.f32.f16.f16.f32 "
                        "{%0,%1,%2,%3}, {%4,%5,%6,%7}, {%8,%9}, {%0,%1,%2,%3};"
                        : "+f"(acc[mt][nt][0]), "+f"(acc[mt][nt][1]),
                          "+f"(acc[mt][nt][2]), "+f"(acc[mt][nt][3])
                        : "r"(af[mt][0]), "r"(af[mt][1]), "r"(af[mt][2]), "r"(af[mt][3]),
                          "r"(bf[nt][0]), "r"(bf[nt][1]));
        }
        __syncthreads();
    }
#undef LOADC

#pragma unroll
    for (int mt = 0; mt < 2; mt++) {
        int r0 = m0 + wm + mt * 16 + (lane >> 2);
#pragma unroll
        for (int nt = 0; nt < 4; nt++) {
            int c = n0 + wn + nt * 8 + 2 * (lane & 3);
            float bx = bias ? bias[c] : 0.f;
            float by = bias ? bias[c + 1] : 0.f;
#pragma unroll
            for (int h = 0; h < 2; h++) {
                int row = r0 + h * 8;
                if (row >= M) continue;
                float vx = acc[mt][nt][h * 2 + 0] + bx;
                float vy = acc[mt][nt][h * 2 + 1] + by;
                if (WRITEF || ACCUM) {
                    float* cp = C + (size_t)row * Nout + c;
                    if (ACCUM) { vx += cp[0]; vy += cp[1]; }
                    cp[0] = vx; cp[1] = vy;
                }
                if (WRITEH) {
                    __half* hp = CH + (size_t)row * Nout + c;
                    hp[0] = __float2half(vx); hp[1] = __float2half(vy);
                }
            }
        }
    }
}

// ---------------- weight preprocessing ----------------
__global__ void trans_qkv_h(const float* __restrict__ Wq, const float* __restrict__ Wk,
                            const float* __restrict__ Wv,
                            const float* __restrict__ bq, const float* __restrict__ bk,
                            const float* __restrict__ bv)
{
    int i = blockIdx.x * blockDim.x + threadIdx.x;
    if (i < NBB * NTT * DD * DD) {
        int bt = i / (DD * DD);
        int b = bt / NTT, t = bt % NTT;
        int r  = i % (DD * DD);
        int n = r / DD, k = r % DD;
        size_t in = (size_t)bt * DD * DD + (size_t)k * DD + n;
        size_t o0 = (((size_t)(b * 3 + 0) * NTT + t)) * DD * DD + r;
        size_t o1 = (((size_t)(b * 3 + 1) * NTT + t)) * DD * DD + r;
        size_t o2 = (((size_t)(b * 3 + 2) * NTT + t)) * DD * DD + r;
        g_WQKVTH[o0] = __float2half(Wq[in]);
        g_WQKVTH[o1] = __float2half(Wk[in]);
        g_WQKVTH[o2] = __float2half(Wv[in]);
    } else {
        int j = i - NBB * NTT * DD * DD;
        if (j < NBB * NTT * DD) {
            int bt = j / DD, c = j % DD;
            int b = bt / NTT, t = bt % NTT;
            g_BQKV[(((size_t)(b * 3 + 0) * NTT + t)) * DD + c] = bq[j];
            g_BQKV[(((size_t)(b * 3 + 1) * NTT + t)) * DD + c] = bk[j];
            g_BQKV[(((size_t)(b * 3 + 2) * NTT + t)) * DD + c] = bv[j];
        }
    }
}

__global__ void wsumT_h(const float* __restrict__ Ws, const float* __restrict__ bs)
{
    int i = blockIdx.x * blockDim.x + threadIdx.x;
    if (i < NBB * DD * DD) {
        int b = i / (DD * DD), r = i % (DD * DD);
        int n = r / DD, k = r % DD;
        float s = 0.f;
#pragma unroll
        for (int t = 0; t < NTT; t++)
            s += Ws[((size_t)b * NTT + t) * DD * DD + (size_t)k * DD + n];
        g_WSUMTH[i] = __float2half(s);
    } else {
        int j = i - NBB * DD * DD;
        if (j < NBB * DD) {
            int b = j / DD, c = j % DD;
            float s = 0.f;
#pragma unroll
            for (int t = 0; t < NTT; t++) s += bs[((size_t)b * NTT + t) * DD + c];
            g_BSUM[j] = s;
        }
    }
}

__global__ void werT_h(const float* __restrict__ We)
{
    int i = blockIdx.x * blockDim.x + threadIdx.x;
    if (i >= NBB * DD * NTT * EHH) return;
    int b = i / (DD * NTT * EHH);
    int r = i % (DD * NTT * EHH);
    int n = r / (NTT * EHH);
    int tj = r % (NTT * EHH);
    g_WERTH[i] = __float2half(We[((size_t)b * NTT * EHH + tj) * DD + n]);
}

__global__ void wqwb_h(const float* __restrict__ We)
{
    int i = blockIdx.x * blockDim.x + threadIdx.x;
    if (i >= NBB * NTT * 64 * DD) return;
    int bt = i / (64 * DD);
    int r  = i % (64 * DD);
    int j = r / DD, k = r % DD;
    g_WQWBH[i] = (j < EHH) ? __float2half(We[((size_t)bt * EHH + j) * DD + k]) : __float2half(0.f);
}

__global__ void w1T_h(const float* __restrict__ W1)
{
    int i = blockIdx.x * blockDim.x + threadIdx.x;
    if (i >= 64 * DD) return;
    int n = i / DD, k = i % DD;
    float v = (n < EHH) ? W1[(size_t)k * EHH + n]
                        : W1[(size_t)(DD + k) * EHH + (n - EHH)];
    g_W1TH[i] = __float2half(v);
}

__global__ void conv_X(const float* __restrict__ x)
{
    size_t i = (size_t)blockIdx.x * blockDim.x + threadIdx.x;
    if (i < NND_C) g_HH[i] = __float2half(x[i]);
}

// ---------------- CSR build keyed by (node, type) ----------------
__global__ void csr_count(const int* __restrict__ EI)
{
    int i = blockIdx.x * blockDim.x + threadIdx.x;
    if (i >= NE9) return;
    int t = i / EE, e = i - t * EE;
    int dst = EI[((size_t)t * 2 + 1) * EE + e];
    atomicAdd(&g_CNT2[dst * NTT + t], 1);
}

__global__ void __launch_bounds__(1024) csr_scan()
{
    __shared__ int sm[1024];
    int tid = threadIdx.x;
    const int CH = (NT9 + 1023) / 1024;
    int lo = tid * CH, hi = lo + CH < NT9 ? lo + CH : NT9;
    int s = 0;
    for (int i = lo; i < hi; i++) s += g_CNT2[i];
    sm[tid] = s;
    __syncthreads();
    for (int off = 1; off < 1024; off <<= 1) {
        int v = (tid >= off) ? sm[tid - off] : 0;
        __syncthreads();
        sm[tid] += v;
        __syncthreads();
    }
    int run = (tid > 0) ? sm[tid - 1] : 0;
    for (int i = lo; i < hi; i++) {
        int c = g_CNT2[i];
        g_CNT2[i] = run;
        g_POS2[i] = run;
        run += c;
    }
    if (tid == 1023) g_CNT2[NT9] = sm[1023];
}

__global__ void csr_fill(const int* __restrict__ EI)
{
    int i = blockIdx.x * blockDim.x + threadIdx.x;
    if (i >= NE9) return;
    int t = i / EE, e = i - t * EE;
    int dst = EI[((size_t)t * 2 + 1) * EE + e];
    int src = EI[((size_t)t * 2 + 0) * EE + e];
    int p = atomicAdd(&g_POS2[dst * NTT + t], 1);
    g_CSRE[p] = i;
    g_CSRS[p] = src;
}

// ---------------- edge MLP (reads packed XSD) ----------------
__global__ void edge_mlp(const int* __restrict__ EI, const float* __restrict__ EA,
                         const float* __restrict__ W1, const float* __restrict__ b1,
                         const float* __restrict__ W2, const float* __restrict__ b2)
{
    __shared__ float sW1e[EDIN * EHH];
    __shared__ float sW2[EHH * EHH];
    __shared__ float sb1[EHH], sb2[EHH];
    int tid = threadIdx.x;
    for (int i = tid; i < EDIN * EHH; i += blockDim.x) sW1e[i] = W1[640 * EHH + i];
    for (int i = tid; i < EHH * EHH; i += blockDim.x)  sW2[i]  = W2[i];
    if (tid < EHH) { sb1[tid] = b1[tid]; sb2[tid] = b2[tid]; }
    __syncthreads();

    long w = (long)blockIdx.x * (blockDim.x / 32) + tid / 32;
    int lane = tid & 31;
    if (w >= (long)NE9) return;
    int t = (int)(w / EE);
    int e = (int)(w % EE);
    int src = EI[((size_t)t * 2 + 0) * EE + e];
    int dst = EI[((size_t)t * 2 + 1) * EE + e];

    float eav = 0.f;
    if (lane < EDIN) eav = EA[((size_t)t * EE + e) * EDIN + lane];

    float h = sb1[lane] + g_XSD[(size_t)src * 64 + lane] + g_XSD[(size_t)dst * 64 + 32 + lane];
#pragma unroll
    for (int i = 0; i < EDIN; i++)
        h += __shfl_sync(0xffffffffu, eav, i) * sW1e[i * EHH + lane];
    h = h > 0.f ? h : 0.01f * h;

    float o = sb2[lane];
#pragma unroll
    for (int i = 0; i < EHH; i++)
        o += __shfl_sync(0xffffffffu, h, i) * sW2[i * EHH + lane];

    g_NEAH[((size_t)t * EE + e) * EHH + lane] = __float2half(o);
}

// ---------------- single-sweep fused attention (warp per node) ----------------
// For each (node, type) segment: S = sum ex_i*v_i, den = sum ex_i, out = S/(den+1e-16);
// be contribution = (den/(den+1e-16))*be_t; WNEA = (sum ex_i*nea_i)/(den+1e-16).
__global__ void __launch_bounds__(256) att_fused(const float* __restrict__ be_b)
{
    __shared__ __align__(8) float sBE[NTT * DD];
    int tid = threadIdx.x;
    for (int j = tid; j < NTT * DD; j += 256) sBE[j] = be_b[j];
    __syncthreads();

    int wrp = tid >> 5, lane = tid & 31;
    int node = blockIdx.x * 8 + wrp;
    if (node >= NN) return;

    float2 acc[5];
    float2* accp = (float2*)(g_ACC + (size_t)node * DD);
#pragma unroll
    for (int i = 0; i < 5; i++) acc[i] = accp[lane + 32 * i];

    __half* wn = g_WNEAH + (size_t)node * (NTT * EHH);
    const float2* sBE2 = (const float2*)sBE;

#pragma unroll 1
    for (int t = 0; t < NTT; t++) {
        int base = g_CNT2[node * NTT + t];
        int endp = g_CNT2[node * NTT + t + 1];
        float wnl = 0.f;
        if (endp > base) {
            float qw = g_QW[((size_t)t * NN + node) * 64 + lane];
            const __half2* q2 = (const __half2*)(g_QKVH + ((size_t)t * NN + node) * DD);
            float2 q[5];
#pragma unroll
            for (int i = 0; i < 5; i++) q[i] = __half22float2(q2[lane + 32 * i]);

            float2 tmp[5];
#pragma unroll
            for (int i = 0; i < 5; i++) tmp[i] = make_float2(0.f, 0.f);
            float den = 0.f;

            for (int idx = base; idx < endp; idx++) {
                int pe  = g_CSRE[idx];
                int src = g_CSRS[idx];
                const __half2* k2 = (const __half2*)(g_QKVH + (size_t)NTT * NND_C
                                                     + ((size_t)t * NN + src) * DD);
                const __half2* v2 = (const __half2*)(g_QKVH + (size_t)2 * NTT * NND_C
                                                     + ((size_t)t * NN + src) * DD);
                float ne = __half2float(g_NEAH[(size_t)pe * EHH + lane]);
                float s = qw * ne;
                float2 vv[5];
#pragma unroll
                for (int i = 0; i < 5; i++) {
                    float2 kk = __half22float2(k2[lane + 32 * i]);
                    vv[i] = __half22float2(v2[lane + 32 * i]);
                    s += q[i].x * kk.x + q[i].y * kk.y;
                }
#pragma unroll
                for (int off = 16; off; off >>= 1) s += __shfl_xor_sync(0xffffffffu, s, off);
                float ex = expf(s * 0.05590169943749474f);
                den += ex;
#pragma unroll
                for (int i = 0; i < 5; i++) {
                    tmp[i].x += ex * vv[i].x;
                    tmp[i].y += ex * vv[i].y;
                }
                wnl += ex * ne;
            }

            float inv = 1.f / (den + 1e-16f);
            float sw  = den * inv;
#pragma unroll
            for (int i = 0; i < 5; i++) {
                float2 bb = sBE2[t * 160 + lane + 32 * i];
                acc[i].x += tmp[i].x * inv + sw * bb.x;
                acc[i].y += tmp[i].y * inv + sw * bb.y;
            }
            wnl *= inv;
        }
        wn[t * EHH + lane] = __float2half(wnl);
    }

#pragma unroll
    for (int i = 0; i < 5; i++) accp[lane + 32 * i] = acc[i];
}

// ---------------- norm / residual / pooling ----------------
__global__ void count_nodes(const int* __restrict__ batch)
{
    int i = blockIdx.x * blockDim.x + threadIdx.x;
    if (i < NN) atomicAdd(&g_GC[batch[i]], 1);
}

__global__ void gstats(const int* __restrict__ batch)
{
    int w = blockIdx.x * (blockDim.x / 32) + threadIdx.x / 32;
    int lane = threadIdx.x & 31;
    if (w >= NN) return;
    const float* a = g_ACC + (size_t)w * DD;
    float s1 = 0.f, s2 = 0.f;
#pragma unroll
    for (int c = lane; c < DD; c += 32) {
        float v = a[c] * (1.f / 9.f);
        v = v > 0.f ? v : 0.01f * v;
        s1 += v; s2 += v * v;
    }
#pragma unroll
    for (int off = 16; off; off >>= 1) {
        s1 += __shfl_xor_sync(0xffffffffu, s1, off);
        s2 += __shfl_xor_sync(0xffffffffu, s2, off);
    }
    if (lane == 0) {
        int g = batch[w];
        atomicAdd(&g_GS[g], s1);
        atomicAdd(&g_GQ[g], s2);
    }
}

__global__ void gfinal()
{
    int g = blockIdx.x * blockDim.x + threadIdx.x;
    if (g >= GG) return;
    float cnt  = (float)g_GC[g];
    float norm = fmaxf(cnt, 1.f) * (float)DD;
    float mean = g_GS[g] / norm;
    float var  = fmaxf(g_GQ[g] / norm - mean * mean, 0.f);
    g_MEAN[g] = mean;
    g_RSTD[g] = rsqrtf(var + 1e-5f);
}

__device__ __forceinline__ unsigned fkey(float f)
{
    unsigned u = __float_as_uint(f);
    return (u & 0x80000000u) ? ~u : (u | 0x80000000u);
}
__device__ __forceinline__ float funkey(unsigned u)
{
    return (u & 0x80000000u) ? __uint_as_float(u & 0x7FFFFFFFu) : __uint_as_float(~u);
}

template<bool WRITEH, bool MAXRED>
__global__ void hupdate(const int* __restrict__ batch,
                        const float* __restrict__ gamma, const float* __restrict__ beta)
{
    size_t i = (size_t)blockIdx.x * blockDim.x + threadIdx.x;
    if (i >= NND_C) return;
    int node = (int)(i / DD), c = (int)(i % DD);
    int g = batch[node];
    float v = g_ACC[i] * (1.f / 9.f);
    v = v > 0.f ? v : 0.01f * v;
    float xn = (v - g_MEAN[g]) * g_RSTD[g] * gamma[c] + beta[c];
    float hn = 0.5f * (g_H[i] + xn);
    g_H[i] = hn;
    if (WRITEH) g_HH[i] = __float2half(hn);
    if (MAXRED) atomicMax(&g_OUTU[(size_t)g * DD + c], fkey(hn));
}

__global__ void finalize(float* __restrict__ out)
{
    int i = blockIdx.x * blockDim.x + threadIdx.x;
    if (i < GG * DD) out[i] = funkey(g_OUTU[i]);
}

// ---------------- host orchestration ----------------
extern "C" void kernel_launch(void* const* d_in, const int* in_sizes, int n_in,
                              void* d_out, int out_size)
{
    const float* x     = (const float*)d_in[0];
    const int*   batch = (const int*)d_in[1];
    const int*   EI    = (const int*)d_in[2];
    const float* EA    = (const float*)d_in[3];
    const float* W1    = (const float*)d_in[4];
    const float* b1    = (const float*)d_in[5];
    const float* W2    = (const float*)d_in[6];
    const float* b2    = (const float*)d_in[7];
    const float* Wq    = (const float*)d_in[8];
    const float* bq    = (const float*)d_in[9];
    const float* Wk    = (const float*)d_in[10];
    const float* bk    = (const float*)d_in[11];
    const float* Wv    = (const float*)d_in[12];
    const float* bv    = (const float*)d_in[13];
    const float* We    = (const float*)d_in[14];
    const float* be    = (const float*)d_in[15];
    const float* Ws    = (const float*)d_in[16];
    const float* bs    = (const float*)d_in[17];
    const float* gamma = (const float*)d_in[18];
    const float* beta  = (const float*)d_in[19];
    float* out = (float*)d_out;

    float *pQW, *pACC, *pH, *pXSD, *pGS, *pGQ, *pBSUM, *pBQKV;
    __half *pQKVH, *pHH, *pWNEAH, *pWQKVTH, *pWSUMTH, *pWERTH, *pWQWBH, *pW1TH;
    int *pGC, *pCNT2;
    unsigned *pOUTU;
    cudaGetSymbolAddress((void**)&pXSD,     g_XSD);
    cudaGetSymbolAddress((void**)&pQKVH,    g_QKVH);
    cudaGetSymbolAddress((void**)&pQW,      g_QW);
    cudaGetSymbolAddress((void**)&pWNEAH,   g_WNEAH);
    cudaGetSymbolAddress((void**)&pACC,     g_ACC);
    cudaGetSymbolAddress((void**)&pH,       g_H);
    cudaGetSymbolAddress((void**)&pHH,      g_HH);
    cudaGetSymbolAddress((void**)&pGS,      g_GS);
    cudaGetSymbolAddress((void**)&pGQ,      g_GQ);
    cudaGetSymbolAddress((void**)&pGC,      g_GC);
    cudaGetSymbolAddress((void**)&pCNT2,    g_CNT2);
    cudaGetSymbolAddress((void**)&pBSUM,    g_BSUM);
    cudaGetSymbolAddress((void**)&pBQKV,    g_BQKV);
    cudaGetSymbolAddress((void**)&pWQKVTH,  g_WQKVTH);
    cudaGetSymbolAddress((void**)&pWSUMTH,  g_WSUMTH);
    cudaGetSymbolAddress((void**)&pWERTH,   g_WERTH);
    cudaGetSymbolAddress((void**)&pWQWBH,   g_WQWBH);
    cudaGetSymbolAddress((void**)&pW1TH,    g_W1TH);
    cudaGetSymbolAddress((void**)&pOUTU,    g_OUTU);

    const int MT = (NN + 127) / 128;        // 391
    const long NND = (long)NN * DD;

    // ---- preprocessing ----
    cudaMemsetAsync(pGC, 0, GG * sizeof(int));
    cudaMemsetAsync(pOUTU, 0, (size_t)GG * DD * sizeof(unsigned));
    count_nodes<<<(NN + 255) / 256, 256>>>(batch);

    trans_qkv_h<<<(NBB * NTT * DD * DD + NBB * NTT * DD + 255) / 256, 256>>>(Wq, Wk, Wv, bq, bk, bv);
    wsumT_h<<<(NBB * DD * DD + NBB * DD + 255) / 256, 256>>>(Ws, bs);
    werT_h<<<(NBB * DD * NTT * EHH + 255) / 256, 256>>>(We);
    wqwb_h<<<(NBB * NTT * 64 * DD + 255) / 256, 256>>>(We);
    w1T_h<<<(64 * DD + 255) / 256, 256>>>(W1);

    cudaMemsetAsync(pCNT2, 0, (NT9 + 1) * sizeof(int));
    csr_count<<<(NE9 + 255) / 256, 256>>>(EI);
    csr_scan<<<1, 1024>>>();
    csr_fill<<<(NE9 + 255) / 256, 256>>>(EI);

    cudaMemcpyAsync(pH, x, NND * sizeof(float), cudaMemcpyDeviceToDevice);
    conv_X<<<(unsigned)((NND + 255) / 256), 256>>>(x);

    // XSD = HH @ [W1src|W1dst]^T
    hgemm<false, true, false><<<dim3(1, MT, 1), 256>>>(
        pHH, pW1TH, nullptr, pXSD, nullptr, NN, DD, 64, 0, 0, 0, 0);
    edge_mlp<<<(NE9 + 7) / 8, 256>>>(EI, EA, W1, b1, W2, b2);

    for (int b = 0; b < NBB; b++) {
        // skip (folded): ACC = HH @ WSUM_b^T + BSUM_b
        hgemm<false, true, false><<<dim3(5, MT, 1), 256>>>(
            pHH, pWSUMTH + (size_t)b * DD * DD, pBSUM + (size_t)b * DD, pACC, nullptr,
            NN, DD, DD, 0, 0, 0, 0);

        // fused Q/K/V (z = 27), fp16 packed output
        hgemm<false, false, true><<<dim3(5, MT, 3 * NTT), 256>>>(
            pHH, pWQKVTH + (size_t)b * 3 * NTT * DD * DD, pBQKV + (size_t)b * 3 * NTT * DD,
            nullptr, pQKVH,
            NN, DD, DD, 0, (long)DD * DD, NND, DD);

        // QW_t = Q_t @ We_t^T (Nout=64, z=9)
        hgemm<false, true, false><<<dim3(1, MT, NTT), 256>>>(
            pQKVH, pWQWBH + (size_t)b * NTT * 64 * DD, nullptr, pQW, nullptr,
            NN, DD, 64, NND, (long)64 * DD, (long)NN * 64, 0);

        // single-sweep fused attention
        att_fused<<<(NN + 7) / 8, 256>>>(be + (size_t)b * NTT * DD);

        // ACC += WNEA @ [stacked We] (K=288)
        hgemm<true, true, false><<<dim3(5, MT, 1), 256>>>(
            pWNEAH, pWERTH + (size_t)b * DD * NTT * EHH, nullptr, pACC, nullptr,
            NN, NTT * EHH, DD, 0, 0, 0, 0);

        cudaMemsetAsync(pGS, 0, GG * sizeof(float));
        cudaMemsetAsync(pGQ, 0, GG * sizeof(float));
        gstats<<<(NN + 7) / 8, 256>>>(batch);
        gfinal<<<1, 256>>>();
        if (b + 1 < NBB)
            hupdate<true, false><<<(unsigned)((NND + 255) / 256), 256>>>(
                batch, gamma + (size_t)b * DD, beta + (size_t)b * DD);
        else
            hupdate<false, true><<<(unsigned)((NND + 255) / 256), 256>>>(
                batch, gamma + (size_t)b * DD, beta + (size_t)b * DD);
    }

    finalize<<<(GG * DD + 255) / 256, 256>>>(out);
}

// round 15
// speedup vs baseline: 1.0283x; 1.0283x over previous
#include <cuda_runtime.h>
#include <cuda_fp16.h>
#include <math.h>
#include <cstdint>

#define NN   50000
#define EE   150000
#define GG   200
#define DD   320
#define EDIN 15
#define EHH  32
#define NBB  3
#define NTT  9
#define NE9  (NTT * EE)
#define NND_C ((size_t)NN * DD)

// ---------------- scratch (static device globals; allocation-free) ----------------
__device__ __half g_NEAH[NTT * EE * EHH];
__device__ float  g_XSD[NN * 64];              // packed [node][0:32]=XS, [32:64]=XD
__device__ __half g_QKVH[3 * NTT * NN * DD];   // [qkv][t][N][D]
__device__ float  g_QW[NTT * NN * 64];
__device__ __half g_WNEAH[NN * NTT * EHH];
__device__ float  g_ACC[NN * DD];
__device__ float  g_H[NN * DD];
__device__ __half g_HH[NN * DD];
__device__ float  g_AL[NE9];                   // CSR-ordered exp(alpha)
__device__ float  g_DEN[NTT * NN];
// fp16 pre-transposed weights, B-operand layout [Nout][K] (K contiguous)
__device__ __half g_WQKVTH[NBB * 3 * NTT * DD * DD];  // [b][qkv][t][n][k]
__device__ float  g_BQKV[NBB * 3 * NTT * DD];
__device__ __half g_WSUMTH[NBB * DD * DD];
__device__ float  g_BSUM[NBB * DD];
__device__ __half g_WERTH[NBB * DD * (NTT * EHH)];  // [b][320][288]
__device__ __half g_WQWBH[NBB * NTT * 64 * DD];     // [bt][64][320], rows 32..63 zero
__device__ __half g_W1TH[64 * DD];                  // rows 0-31: W1src^T, 32-63: W1dst^T
// CSR (node-keyed over all 9 types)
__device__ int   g_CNT[NN + 1];
__device__ int   g_POS[NN];
__device__ int   g_CSRE[NE9];
__device__ int   g_CSRS[NE9];
__device__ int   g_CSRD[NE9];
__device__ float g_GS[GG];
__device__ float g_GQ[GG];
__device__ int   g_GC[GG];
__device__ float g_MEAN[GG];
__device__ float g_RSTD[GG];
__device__ unsigned g_OUTU[GG * DD];

// ---------------- helpers ----------------
__device__ __forceinline__ uint32_t smem_u32(const void* p)
{
    uint32_t a;
    asm("{ .reg .u64 t; cvta.to.shared.u64 t, %1; cvt.u32.u64 %0, t; }" : "=r"(a) : "l"(p));
    return a;
}

__device__ __forceinline__ void cp16(unsigned dst, const void* src, bool p)
{
    asm volatile("cp.async.cg.shared.global [%0], [%1], 16, %2;"
                 :: "r"(dst), "l"(src), "r"(p ? 16 : 0));
}
__device__ __forceinline__ void cp_commit() { asm volatile("cp.async.commit_group;"); }
template<int N> __device__ __forceinline__ void cp_wait() { asm volatile("cp.async.wait_group %0;" :: "n"(N)); }

// ---------------- FP16 tensor-core GEMM (m16n8k16), cp.async double-buffered ----------
template<bool ACCUM, bool WRITEF, bool WRITEH>
__global__ void __launch_bounds__(256) hgemm(
    const __half* __restrict__ A, const __half* __restrict__ B,
    const float* __restrict__ bias, float* __restrict__ C, __half* __restrict__ CH,
    int M, int K, int Nout,
    long aZ, long bZ, long cZ, long biasZ)
{
    __shared__ __align__(16) __half As[2][128 * 40];
    __shared__ __align__(16) __half Bs[2][64 * 40];

    const int z = blockIdx.z;
    A += (size_t)z * aZ; B += (size_t)z * bZ;
    if (WRITEF || ACCUM) C += (size_t)z * cZ;
    if (WRITEH) CH += (size_t)z * cZ;
    if (bias) bias += (size_t)z * biasZ;

    const int tid  = threadIdx.x;
    const int lane = tid & 31;
    const int wid  = tid >> 5;
    const int wm   = (wid & 3) * 32;
    const int wn   = (wid >> 2) * 32;
    const int m0 = blockIdx.y * 128;
    const int n0 = blockIdx.x * 64;

    uint32_t uA[2] = { smem_u32(As[0]), smem_u32(As[1]) };
    uint32_t uB[2] = { smem_u32(Bs[0]), smem_u32(Bs[1]) };

    const int arow = tid >> 2;
    const int acol = (tid & 3) * 8;

    float acc[2][4][4];
#pragma unroll
    for (int mt = 0; mt < 2; mt++)
#pragma unroll
        for (int nt = 0; nt < 4; nt++)
#pragma unroll
            for (int i = 0; i < 4; i++) acc[mt][nt][i] = 0.f;

    const int nk = K / 32;

#define LOADC(c, buf) do {                                                                   \
    int k0_ = (c) * 32;                                                                      \
    int r0_ = m0 + arow;                                                                     \
    cp16(uA[buf] + (unsigned)(arow * 40 + acol) * 2,                                         \
         A + (size_t)r0_ * K + k0_ + acol, r0_ < M);                                         \
    cp16(uA[buf] + (unsigned)((arow + 64) * 40 + acol) * 2,                                  \
         A + (size_t)(r0_ + 64) * K + k0_ + acol, (r0_ + 64) < M);                           \
    cp16(uB[buf] + (unsigned)(arow * 40 + acol) * 2,                                         \
         B + (size_t)(n0 + arow) * K + k0_ + acol, true);                                    \
} while (0)

    LOADC(0, 0);
    cp_commit();

    for (int kt = 0; kt < nk; kt++) {
        int s = kt & 1, o = s ^ 1;
        if (kt + 1 < nk) {
            LOADC(kt + 1, o);
            cp_commit();
            cp_wait<1>();
        } else {
            cp_wait<0>();
        }
        __syncthreads();

        uint32_t uAb = uA[s], uBb = uB[s];
#pragma unroll
        for (int ks = 0; ks < 32; ks += 16) {
            uint32_t af[2][4], bf[4][2];
#pragma unroll
            for (int mt = 0; mt < 2; mt++) {
                int row = wm + mt * 16 + (lane & 15);
                int col = ks + ((lane >> 4) << 3);
                uint32_t addr = uAb + (unsigned)(row * 40 + col) * 2;
                asm volatile("ldmatrix.sync.aligned.m8n8.x4.shared.b16 {%0,%1,%2,%3}, [%4];"
                             : "=r"(af[mt][0]), "=r"(af[mt][1]), "=r"(af[mt][2]), "=r"(af[mt][3])
                             : "r"(addr));
            }
#pragma unroll
            for (int nt = 0; nt < 4; nt++) {
                int row = wn + nt * 8 + (lane & 7);
                int col = ks + (((lane >> 3) & 1) << 3);
                uint32_t addr = uBb + (unsigned)(row * 40 + col) * 2;
                asm volatile("ldmatrix.sync.aligned.m8n8.x2.shared.b16 {%0,%1}, [%2];"
                             : "=r"(bf[nt][0]), "=r"(bf[nt][1]) : "r"(addr));
            }
#pragma unroll
            for (int nt = 0; nt < 4; nt++)
#pragma unroll
                for (int mt = 0; mt < 2; mt++)
                    asm volatile(
                        "mma.sync.aligned.m16n8k16.row.col.f32.f16.f16.f32 "
                        "{%0,%1,%2,%3}, {%4,%5,%6,%7}, {%8,%9}, {%0,%1,%2,%3};"
                        : "+f"(acc[mt][nt][0]), "+f"(acc[mt][nt][1]),
                          "+f"(acc[mt][nt][2]), "+f"(acc[mt][nt][3])
                        : "r"(af[mt][0]), "r"(af[mt][1]), "r"(af[mt][2]), "r"(af[mt][3]),
                          "r"(bf[nt][0]), "r"(bf[nt][1]));
        }
        __syncthreads();
    }
#undef LOADC

#pragma unroll
    for (int mt = 0; mt < 2; mt++) {
        int r0 = m0 + wm + mt * 16 + (lane >> 2);
#pragma unroll
        for (int nt = 0; nt < 4; nt++) {
            int c = n0 + wn + nt * 8 + 2 * (lane & 3);
            float bx = bias ? bias[c] : 0.f;
            float by = bias ? bias[c + 1] : 0.f;
#pragma unroll
            for (int h = 0; h < 2; h++) {
                int row = r0 + h * 8;
                if (row >= M) continue;
                float vx = acc[mt][nt][h * 2 + 0] + bx;
                float vy = acc[mt][nt][h * 2 + 1] + by;
                if (WRITEF || ACCUM) {
                    float* cp = C + (size_t)row * Nout + c;
                    if (ACCUM) { vx += cp[0]; vy += cp[1]; }
                    cp[0] = vx; cp[1] = vy;
                }
                if (WRITEH) {
                    __half* hp = CH + (size_t)row * Nout + c;
                    hp[0] = __float2half(vx); hp[1] = __float2half(vy);
                }
            }
        }
    }
}

// ---------------- weight preprocessing ----------------
__global__ void trans_qkv_h(const float* __restrict__ Wq, const float* __restrict__ Wk,
                            const float* __restrict__ Wv,
                            const float* __restrict__ bq, const float* __restrict__ bk,
                            const float* __restrict__ bv)
{
    int i = blockIdx.x * blockDim.x + threadIdx.x;
    if (i < NBB * NTT * DD * DD) {
        int bt = i / (DD * DD);
        int b = bt / NTT, t = bt % NTT;
        int r  = i % (DD * DD);
        int n = r / DD, k = r % DD;
        size_t in = (size_t)bt * DD * DD + (size_t)k * DD + n;
        size_t o0 = (((size_t)(b * 3 + 0) * NTT + t)) * DD * DD + r;
        size_t o1 = (((size_t)(b * 3 + 1) * NTT + t)) * DD * DD + r;
        size_t o2 = (((size_t)(b * 3 + 2) * NTT + t)) * DD * DD + r;
        g_WQKVTH[o0] = __float2half(Wq[in]);
        g_WQKVTH[o1] = __float2half(Wk[in]);
        g_WQKVTH[o2] = __float2half(Wv[in]);
    } else {
        int j = i - NBB * NTT * DD * DD;
        if (j < NBB * NTT * DD) {
            int bt = j / DD, c = j % DD;
            int b = bt / NTT, t = bt % NTT;
            g_BQKV[(((size_t)(b * 3 + 0) * NTT + t)) * DD + c] = bq[j];
            g_BQKV[(((size_t)(b * 3 + 1) * NTT + t)) * DD + c] = bk[j];
            g_BQKV[(((size_t)(b * 3 + 2) * NTT + t)) * DD + c] = bv[j];
        }
    }
}

__global__ void wsumT_h(const float* __restrict__ Ws, const float* __restrict__ bs)
{
    int i = blockIdx.x * blockDim.x + threadIdx.x;
    if (i < NBB * DD * DD) {
        int b = i / (DD * DD), r = i % (DD * DD);
        int n = r / DD, k = r % DD;
        float s = 0.f;
#pragma unroll
        for (int t = 0; t < NTT; t++)
            s += Ws[((size_t)b * NTT + t) * DD * DD + (size_t)k * DD + n];
        g_WSUMTH[i] = __float2half(s);
    } else {
        int j = i - NBB * DD * DD;
        if (j < NBB * DD) {
            int b = j / DD, c = j % DD;
            float s = 0.f;
#pragma unroll
            for (int t = 0; t < NTT; t++) s += bs[((size_t)b * NTT + t) * DD + c];
            g_BSUM[j] = s;
        }
    }
}

__global__ void werT_h(const float* __restrict__ We)
{
    int i = blockIdx.x * blockDim.x + threadIdx.x;
    if (i >= NBB * DD * NTT * EHH) return;
    int b = i / (DD * NTT * EHH);
    int r = i % (DD * NTT * EHH);
    int n = r / (NTT * EHH);
    int tj = r % (NTT * EHH);
    g_WERTH[i] = __float2half(We[((size_t)b * NTT * EHH + tj) * DD + n]);
}

__global__ void wqwb_h(const float* __restrict__ We)
{
    int i = blockIdx.x * blockDim.x + threadIdx.x;
    if (i >= NBB * NTT * 64 * DD) return;
    int bt = i / (64 * DD);
    int r  = i % (64 * DD);
    int j = r / DD, k = r % DD;
    g_WQWBH[i] = (j < EHH) ? __float2half(We[((size_t)bt * EHH + j) * DD + k]) : __float2half(0.f);
}

__global__ void w1T_h(const float* __restrict__ W1)
{
    int i = blockIdx.x * blockDim.x + threadIdx.x;
    if (i >= 64 * DD) return;
    int n = i / DD, k = i % DD;
    float v = (n < EHH) ? W1[(size_t)k * EHH + n]
                        : W1[(size_t)(DD + k) * EHH + (n - EHH)];
    g_W1TH[i] = __float2half(v);
}

__global__ void conv_X(const float* __restrict__ x)
{
    size_t i = (size_t)blockIdx.x * blockDim.x + threadIdx.x;
    if (i < NND_C) g_HH[i] = __float2half(x[i]);
}

// ---------------- CSR build (node-keyed, all 9 types) ----------------
__global__ void csr_count(const int* __restrict__ EI)
{
    int i = blockIdx.x * blockDim.x + threadIdx.x;
    if (i >= NE9) return;
    int t = i / EE, e = i - t * EE;
    int dst = EI[((size_t)t * 2 + 1) * EE + e];
    atomicAdd(&g_CNT[dst], 1);
}

__global__ void __launch_bounds__(1024) csr_scan()
{
    __shared__ int sm[1024];
    int tid = threadIdx.x;
    const int CH = (NN + 1023) / 1024;
    int lo = tid * CH, hi = lo + CH < NN ? lo + CH : NN;
    int s = 0;
    for (int i = lo; i < hi; i++) s += g_CNT[i];
    sm[tid] = s;
    __syncthreads();
    for (int off = 1; off < 1024; off <<= 1) {
        int v = (tid >= off) ? sm[tid - off] : 0;
        __syncthreads();
        sm[tid] += v;
        __syncthreads();
    }
    int run = (tid > 0) ? sm[tid - 1] : 0;
    for (int i = lo; i < hi; i++) {
        int c = g_CNT[i];
        g_CNT[i] = run;
        g_POS[i] = run;
        run += c;
    }
    if (tid == 1023) g_CNT[NN] = sm[1023];
}

__global__ void csr_fill(const int* __restrict__ EI)
{
    int i = blockIdx.x * blockDim.x + threadIdx.x;
    if (i >= NE9) return;
    int t = i / EE, e = i - t * EE;
    int dst = EI[((size_t)t * 2 + 1) * EE + e];
    int src = EI[((size_t)t * 2 + 0) * EE + e];
    int p = atomicAdd(&g_POS[dst], 1);
    g_CSRE[p] = i;
    g_CSRS[p] = src;
    g_CSRD[p] = dst;
}

// ---------------- edge MLP (reads packed XSD) ----------------
__global__ void edge_mlp(const int* __restrict__ EI, const float* __restrict__ EA,
                         const float* __restrict__ W1, const float* __restrict__ b1,
                         const float* __restrict__ W2, const float* __restrict__ b2)
{
    __shared__ float sW1e[EDIN * EHH];
    __shared__ float sW2[EHH * EHH];
    __shared__ float sb1[EHH], sb2[EHH];
    int tid = threadIdx.x;
    for (int i = tid; i < EDIN * EHH; i += blockDim.x) sW1e[i] = W1[640 * EHH + i];
    for (int i = tid; i < EHH * EHH; i += blockDim.x)  sW2[i]  = W2[i];
    if (tid < EHH) { sb1[tid] = b1[tid]; sb2[tid] = b2[tid]; }
    __syncthreads();

    long w = (long)blockIdx.x * (blockDim.x / 32) + tid / 32;
    int lane = tid & 31;
    if (w >= (long)NE9) return;
    int t = (int)(w / EE);
    int e = (int)(w % EE);
    int src = EI[((size_t)t * 2 + 0) * EE + e];
    int dst = EI[((size_t)t * 2 + 1) * EE + e];

    float eav = 0.f;
    if (lane < EDIN) eav = EA[((size_t)t * EE + e) * EDIN + lane];

    float h = sb1[lane] + g_XSD[(size_t)src * 64 + lane] + g_XSD[(size_t)dst * 64 + 32 + lane];
#pragma unroll
    for (int i = 0; i < EDIN; i++)
        h += __shfl_sync(0xffffffffu, eav, i) * sW1e[i * EHH + lane];
    h = h > 0.f ? h : 0.01f * h;

    float o = sb2[lane];
#pragma unroll
    for (int i = 0; i < EHH; i++)
        o += __shfl_sync(0xffffffffu, h, i) * sW2[i * EHH + lane];

    g_NEAH[((size_t)t * EE + e) * EHH + lane] = __float2half(o);
}

// ---------------- attention (CSR-ordered pass1; no-amax softmax) ----------------
__global__ void att_pass1()
{
    long idx = (long)blockIdx.x * 8 + (threadIdx.x >> 5);
    int lane = threadIdx.x & 31;
    if (idx >= NE9) return;
    int pe  = g_CSRE[idx];
    int src = g_CSRS[idx];
    int dst = g_CSRD[idx];
    int t = pe / EE;
    const __half2* q2 = (const __half2*)(g_QKVH + ((size_t)t * NN + dst) * DD);
    const __half2* k2 = (const __half2*)(g_QKVH + (size_t)NTT * NND_C + ((size_t)t * NN + src) * DD);
    float s = g_QW[((size_t)t * NN + dst) * 64 + lane]
            * __half2float(g_NEAH[(size_t)pe * EHH + lane]);
#pragma unroll
    for (int i = 0; i < 5; i++) {
        float2 qa = __half22float2(q2[lane + 32 * i]);
        float2 kb = __half22float2(k2[lane + 32 * i]);
        s += qa.x * kb.x + qa.y * kb.y;
    }
#pragma unroll
    for (int off = 16; off; off >>= 1) s += __shfl_xor_sync(0xffffffffu, s, off);
    if (lane == 0) {
        float ex = expf(s * 0.05590169943749474f);
        g_AL[idx] = ex;
        atomicAdd(&g_DEN[(size_t)t * NN + dst], ex);
    }
}

// per-half gather body: channels float2 [I0, I0+NI), DONEA -> NEA/WNEA duty
template<int I0, int NI, bool DONEA>
__device__ __forceinline__ void gather_half(int node, int lane,
                                            const float2* sBE2, float* sSWrow, float* sWrow)
{
    float2 acc[NI];
    float2* accp = (float2*)(g_ACC + (size_t)node * DD);
#pragma unroll
    for (int i = 0; i < NI; i++) acc[i] = accp[lane + 32 * (I0 + i)];

    int start = g_CNT[node], end = g_CNT[node + 1];
    for (int idx = start; idx < end; idx++) {
        int pe  = g_CSRE[idx];
        int src = g_CSRS[idx];
        int t = pe / EE;
        float w = g_AL[idx] / (g_DEN[(size_t)t * NN + node] + 1e-16f);
        const __half2* v2 = (const __half2*)(g_QKVH + (size_t)2 * NTT * NND_C
                                             + ((size_t)t * NN + src) * DD);
#pragma unroll
        for (int i = 0; i < NI; i++) {
            float2 vv = __half22float2(v2[lane + 32 * (I0 + i)]);
            acc[i].x += w * vv.x;
            acc[i].y += w * vv.y;
        }
        if (DONEA)
            sWrow[t * EHH + lane] += w * __half2float(g_NEAH[(size_t)pe * EHH + lane]);
        if (lane == 0) sSWrow[t] += w;
    }
    __syncwarp();

#pragma unroll
    for (int t = 0; t < NTT; t++) {
        float swt = sSWrow[t];
        if (swt != 0.f) {
#pragma unroll
            for (int i = 0; i < NI; i++) {
                float2 bb = sBE2[t * 160 + lane + 32 * (I0 + i)];
                acc[i].x += swt * bb.x;
                acc[i].y += swt * bb.y;
            }
        }
    }

#pragma unroll
    for (int i = 0; i < NI; i++) accp[lane + 32 * (I0 + i)] = acc[i];

    if (DONEA) {
        __half* wn = g_WNEAH + (size_t)node * (NTT * EHH);
#pragma unroll
        for (int t = 0; t < NTT; t++) wn[t * EHH + lane] = __float2half(sWrow[t * EHH + lane]);
    }
}

// 2 warps per node: warp half 0 -> float2 chunks 0..2 (channels 0-191),
// warp half 1 -> chunks 3..4 (192-319) + NEA/WNEA.
__global__ void __launch_bounds__(256) att_gather(const float* __restrict__ be_b)
{
    __shared__ float sW[4][NTT * EHH];
    __shared__ float sSW[8][NTT];
    __shared__ __align__(8) float sBE[NTT * DD];

    int tid = threadIdx.x;
    for (int j = tid; j < NTT * DD; j += 256) sBE[j] = be_b[j];

    int wrp = tid >> 5, lane = tid & 31;
    int nw = wrp >> 1, half = wrp & 1;
    int node = blockIdx.x * 4 + nw;
    if (half)
        for (int j = lane; j < NTT * EHH; j += 32) sW[nw][j] = 0.f;
    if (lane < NTT) sSW[wrp][lane] = 0.f;
    __syncthreads();
    if (node >= NN) return;

    const float2* sBE2 = (const float2*)sBE;
    if (half == 0)
        gather_half<0, 3, false>(node, lane, sBE2, sSW[wrp], nullptr);
    else
        gather_half<3, 2, true >(node, lane, sBE2, sSW[wrp], sW[nw]);
}

// ---------------- norm / residual / pooling ----------------
__global__ void count_nodes(const int* __restrict__ batch)
{
    int i = blockIdx.x * blockDim.x + threadIdx.x;
    if (i < NN) atomicAdd(&g_GC[batch[i]], 1);
}

__global__ void gstats(const int* __restrict__ batch)
{
    int w = blockIdx.x * (blockDim.x / 32) + threadIdx.x / 32;
    int lane = threadIdx.x & 31;
    if (w >= NN) return;
    const float* a = g_ACC + (size_t)w * DD;
    float s1 = 0.f, s2 = 0.f;
#pragma unroll
    for (int c = lane; c < DD; c += 32) {
        float v = a[c] * (1.f / 9.f);
        v = v > 0.f ? v : 0.01f * v;
        s1 += v; s2 += v * v;
    }
#pragma unroll
    for (int off = 16; off; off >>= 1) {
        s1 += __shfl_xor_sync(0xffffffffu, s1, off);
        s2 += __shfl_xor_sync(0xffffffffu, s2, off);
    }
    if (lane == 0) {
        int g = batch[w];
        atomicAdd(&g_GS[g], s1);
        atomicAdd(&g_GQ[g], s2);
    }
}

__global__ void gfinal()
{
    int g = blockIdx.x * blockDim.x + threadIdx.x;
    if (g >= GG) return;
    float cnt  = (float)g_GC[g];
    float norm = fmaxf(cnt, 1.f) * (float)DD;
    float mean = g_GS[g] / norm;
    float var  = fmaxf(g_GQ[g] / norm - mean * mean, 0.f);
    g_MEAN[g] = mean;
    g_RSTD[g] = rsqrtf(var + 1e-5f);
}

__device__ __forceinline__ unsigned fkey(float f)
{
    unsigned u = __float_as_uint(f);
    return (u & 0x80000000u) ? ~u : (u | 0x80000000u);
}
__device__ __forceinline__ float funkey(unsigned u)
{
    return (u & 0x80000000u) ? __uint_as_float(u & 0x7FFFFFFFu) : __uint_as_float(~u);
}

template<bool WRITEH, bool MAXRED>
__global__ void hupdate(const int* __restrict__ batch,
                        const float* __restrict__ gamma, const float* __restrict__ beta)
{
    size_t i = (size_t)blockIdx.x * blockDim.x + threadIdx.x;
    if (i >= NND_C) return;
    int node = (int)(i / DD), c = (int)(i % DD);
    int g = batch[node];
    float v = g_ACC[i] * (1.f / 9.f);
    v = v > 0.f ? v : 0.01f * v;
    float xn = (v - g_MEAN[g]) * g_RSTD[g] * gamma[c] + beta[c];
    float hn = 0.5f * (g_H[i] + xn);
    g_H[i] = hn;
    if (WRITEH) g_HH[i] = __float2half(hn);
    if (MAXRED) atomicMax(&g_OUTU[(size_t)g * DD + c], fkey(hn));
}

__global__ void finalize(float* __restrict__ out)
{
    int i = blockIdx.x * blockDim.x + threadIdx.x;
    if (i < GG * DD) out[i] = funkey(g_OUTU[i]);
}

// ---------------- host orchestration ----------------
extern "C" void kernel_launch(void* const* d_in, const int* in_sizes, int n_in,
                              void* d_out, int out_size)
{
    const float* x     = (const float*)d_in[0];
    const int*   batch = (const int*)d_in[1];
    const int*   EI    = (const int*)d_in[2];
    const float* EA    = (const float*)d_in[3];
    const float* W1    = (const float*)d_in[4];
    const float* b1    = (const float*)d_in[5];
    const float* W2    = (const float*)d_in[6];
    const float* b2    = (const float*)d_in[7];
    const float* Wq    = (const float*)d_in[8];
    const float* bq    = (const float*)d_in[9];
    const float* Wk    = (const float*)d_in[10];
    const float* bk    = (const float*)d_in[11];
    const float* Wv    = (const float*)d_in[12];
    const float* bv    = (const float*)d_in[13];
    const float* We    = (const float*)d_in[14];
    const float* be    = (const float*)d_in[15];
    const float* Ws    = (const float*)d_in[16];
    const float* bs    = (const float*)d_in[17];
    const float* gamma = (const float*)d_in[18];
    const float* beta  = (const float*)d_in[19];
    float* out = (float*)d_out;

    float *pQW, *pACC, *pH, *pXSD, *pGS, *pGQ, *pBSUM, *pBQKV, *pDEN;
    __half *pQKVH, *pHH, *pWNEAH, *pWQKVTH, *pWSUMTH, *pWERTH, *pWQWBH, *pW1TH;
    int *pGC, *pCNT;
    unsigned *pOUTU;
    cudaGetSymbolAddress((void**)&pXSD,     g_XSD);
    cudaGetSymbolAddress((void**)&pQKVH,    g_QKVH);
    cudaGetSymbolAddress((void**)&pQW,      g_QW);
    cudaGetSymbolAddress((void**)&pWNEAH,   g_WNEAH);
    cudaGetSymbolAddress((void**)&pACC,     g_ACC);
    cudaGetSymbolAddress((void**)&pH,       g_H);
    cudaGetSymbolAddress((void**)&pHH,      g_HH);
    cudaGetSymbolAddress((void**)&pGS,      g_GS);
    cudaGetSymbolAddress((void**)&pGQ,      g_GQ);
    cudaGetSymbolAddress((void**)&pGC,      g_GC);
    cudaGetSymbolAddress((void**)&pCNT,     g_CNT);
    cudaGetSymbolAddress((void**)&pBSUM,    g_BSUM);
    cudaGetSymbolAddress((void**)&pBQKV,    g_BQKV);
    cudaGetSymbolAddress((void**)&pDEN,     g_DEN);
    cudaGetSymbolAddress((void**)&pWQKVTH,  g_WQKVTH);
    cudaGetSymbolAddress((void**)&pWSUMTH,  g_WSUMTH);
    cudaGetSymbolAddress((void**)&pWERTH,   g_WERTH);
    cudaGetSymbolAddress((void**)&pWQWBH,   g_WQWBH);
    cudaGetSymbolAddress((void**)&pW1TH,    g_W1TH);
    cudaGetSymbolAddress((void**)&pOUTU,    g_OUTU);

    const int MT = (NN + 127) / 128;        // 391
    const long NND = (long)NN * DD;

    // ---- preprocessing ----
    cudaMemsetAsync(pGC, 0, GG * sizeof(int));
    cudaMemsetAsync(pOUTU, 0, (size_t)GG * DD * sizeof(unsigned));
    count_nodes<<<(NN + 255) / 256, 256>>>(batch);

    trans_qkv_h<<<(NBB * NTT * DD * DD + NBB * NTT * DD + 255) / 256, 256>>>(Wq, Wk, Wv, bq, bk, bv);
    wsumT_h<<<(NBB * DD * DD + NBB * DD + 255) / 256, 256>>>(Ws, bs);
    werT_h<<<(NBB * DD * NTT * EHH + 255) / 256, 256>>>(We);
    wqwb_h<<<(NBB * NTT * 64 * DD + 255) / 256, 256>>>(We);
    w1T_h<<<(64 * DD + 255) / 256, 256>>>(W1);

    cudaMemsetAsync(pCNT, 0, (NN + 1) * sizeof(int));
    csr_count<<<(NE9 + 255) / 256, 256>>>(EI);
    csr_scan<<<1, 1024>>>();
    csr_fill<<<(NE9 + 255) / 256, 256>>>(EI);

    cudaMemcpyAsync(pH, x, NND * sizeof(float), cudaMemcpyDeviceToDevice);
    conv_X<<<(unsigned)((NND + 255) / 256), 256>>>(x);

    // XSD = HH @ [W1src|W1dst]^T
    hgemm<false, true, false><<<dim3(1, MT, 1), 256>>>(
        pHH, pW1TH, nullptr, pXSD, nullptr, NN, DD, 64, 0, 0, 0, 0);
    edge_mlp<<<(NE9 + 7) / 8, 256>>>(EI, EA, W1, b1, W2, b2);

    for (int b = 0; b < NBB; b++) {
        // skip (folded): ACC = HH @ WSUM_b^T + BSUM_b
        hgemm<false, true, false><<<dim3(5, MT, 1), 256>>>(
            pHH, pWSUMTH + (size_t)b * DD * DD, pBSUM + (size_t)b * DD, pACC, nullptr,
            NN, DD, DD, 0, 0, 0, 0);

        // fused Q/K/V (z = 27), fp16 packed output
        hgemm<false, false, true><<<dim3(5, MT, 3 * NTT), 256>>>(
            pHH, pWQKVTH + (size_t)b * 3 * NTT * DD * DD, pBQKV + (size_t)b * 3 * NTT * DD,
            nullptr, pQKVH,
            NN, DD, DD, 0, (long)DD * DD, NND, DD);

        // QW_t = Q_t @ We_t^T (Nout=64, z=9)
        hgemm<false, true, false><<<dim3(1, MT, NTT), 256>>>(
            pQKVH, pWQWBH + (size_t)b * NTT * 64 * DD, nullptr, pQW, nullptr,
            NN, DD, 64, NND, (long)64 * DD, (long)NN * 64, 0);

        cudaMemsetAsync(pDEN, 0, (size_t)NTT * NN * sizeof(float));
        att_pass1<<<(NE9 + 7) / 8, 256>>>();
        att_gather<<<(NN + 3) / 4, 256>>>(be + (size_t)b * NTT * DD);

        // ACC += WNEA @ [stacked We] (K=288)
        hgemm<true, true, false><<<dim3(5, MT, 1), 256>>>(
            pWNEAH, pWERTH + (size_t)b * DD * NTT * EHH, nullptr, pACC, nullptr,
            NN, NTT * EHH, DD, 0, 0, 0, 0);

        cudaMemsetAsync(pGS, 0, GG * sizeof(float));
        cudaMemsetAsync(pGQ, 0, GG * sizeof(float));
        gstats<<<(NN + 7) / 8, 256>>>(batch);
        gfinal<<<1, 256>>>();
        if (b + 1 < NBB)
            hupdate<true, false><<<(unsigned)((NND + 255) / 256), 256>>>(
                batch, gamma + (size_t)b * DD, beta + (size_t)b * DD);
        else
            hupdate<false, true><<<(unsigned)((NND + 255) / 256), 256>>>(
                batch, gamma + (size_t)b * DD, beta + (size_t)b * DD);
    }

    finalize<<<(GG * DD + 255) / 256, 256>>>(out);
}

// round 16
// speedup vs baseline: 1.0440x; 1.0153x over previous
#include <cuda_runtime.h>
#include <cuda_fp16.h>
#include <math.h>
#include <cstdint>

#define NN   50000
#define EE   150000
#define GG   200
#define DD   320
#define EDIN 15
#define EHH  32
#define NBB  3
#define NTT  9
#define NE9  (NTT * EE)
#define NND_C ((size_t)NN * DD)

// ---------------- scratch (static device globals; allocation-free) ----------------
__device__ __half g_NEAH[NTT * EE * EHH];      // edge-order (written by edge_mlp)
__device__ __half g_NEAC[NE9 * EHH];           // CSR-order copy (hot loops)
__device__ float  g_XSD[NN * 64];              // packed [node][0:32]=XS, [32:64]=XD
__device__ __half g_QKVH[3 * NTT * NN * DD];   // [qkv][t][N][D]
__device__ float  g_QW[NTT * NN * 64];
__device__ __half g_WNEAH[NN * NTT * EHH];
__device__ float  g_ACC[NN * DD];
__device__ float  g_H[NN * DD];
__device__ __half g_HH[NN * DD];
__device__ float  g_AL[NE9];                   // CSR-ordered exp(alpha)
__device__ float  g_DEN[NTT * NN];
// fp16 pre-transposed weights, B-operand layout [Nout][K] (K contiguous)
__device__ __half g_WQKVTH[NBB * 3 * NTT * DD * DD];  // [b][qkv][t][n][k]
__device__ float  g_BQKV[NBB * 3 * NTT * DD];
__device__ __half g_WSUMTH[NBB * DD * DD];
__device__ float  g_BSUM[NBB * DD];
__device__ __half g_WERTH[NBB * DD * (NTT * EHH)];  // [b][320][288]
__device__ __half g_WQWBH[NBB * NTT * 64 * DD];     // [bt][64][320], rows 32..63 zero
__device__ __half g_W1TH[64 * DD];                  // rows 0-31: W1src^T, 32-63: W1dst^T
// CSR (node-keyed over all 9 types)
__device__ int   g_CNT[NN + 1];
__device__ int   g_POS[NN];
__device__ int   g_CSRE[NE9];                  // pe = t*EE+e (only for NEA reorder)
__device__ int   g_CSRS[NE9];                  // src node
__device__ int   g_CSRTD[NE9];                 // (t<<16) | dst
__device__ float g_GS[GG];
__device__ float g_GQ[GG];
__device__ int   g_GC[GG];
__device__ float g_MEAN[GG];
__device__ float g_RSTD[GG];
__device__ unsigned g_OUTU[GG * DD];

// ---------------- helpers ----------------
__device__ __forceinline__ uint32_t smem_u32(const void* p)
{
    uint32_t a;
    asm("{ .reg .u64 t; cvta.to.shared.u64 t, %1; cvt.u32.u64 %0, t; }" : "=r"(a) : "l"(p));
    return a;
}

__device__ __forceinline__ void cp16(unsigned dst, const void* src, bool p)
{
    asm volatile("cp.async.cg.shared.global [%0], [%1], 16, %2;"
                 :: "r"(dst), "l"(src), "r"(p ? 16 : 0));
}
__device__ __forceinline__ void cp_commit() { asm volatile("cp.async.commit_group;"); }
template<int N> __device__ __forceinline__ void cp_wait() { asm volatile("cp.async.wait_group %0;" :: "n"(N)); }

// ---------------- FP16 tensor-core GEMM (m16n8k16), cp.async double-buffered ----------
template<bool ACCUM, bool WRITEF, bool WRITEH>
__global__ void __launch_bounds__(256) hgemm(
    const __half* __restrict__ A, const __half* __restrict__ B,
    const float* __restrict__ bias, float* __restrict__ C, __half* __restrict__ CH,
    int M, int K, int Nout,
    long aZ, long bZ, long cZ, long biasZ)
{
    __shared__ __align__(16) __half As[2][128 * 40];
    __shared__ __align__(16) __half Bs[2][64 * 40];

    const int z = blockIdx.z;
    A += (size_t)z * aZ; B += (size_t)z * bZ;
    if (WRITEF || ACCUM) C += (size_t)z * cZ;
    if (WRITEH) CH += (size_t)z * cZ;
    if (bias) bias += (size_t)z * biasZ;

    const int tid  = threadIdx.x;
    const int lane = tid & 31;
    const int wid  = tid >> 5;
    const int wm   = (wid & 3) * 32;
    const int wn   = (wid >> 2) * 32;
    const int m0 = blockIdx.y * 128;
    const int n0 = blockIdx.x * 64;

    uint32_t uA[2] = { smem_u32(As[0]), smem_u32(As[1]) };
    uint32_t uB[2] = { smem_u32(Bs[0]), smem_u32(Bs[1]) };

    const int arow = tid >> 2;
    const int acol = (tid & 3) * 8;

    float acc[2][4][4];
#pragma unroll
    for (int mt = 0; mt < 2; mt++)
#pragma unroll
        for (int nt = 0; nt < 4; nt++)
#pragma unroll
            for (int i = 0; i < 4; i++) acc[mt][nt][i] = 0.f;

    const int nk = K / 32;

#define LOADC(c, buf) do {                                                                   \
    int k0_ = (c) * 32;                                                                      \
    int r0_ = m0 + arow;                                                                     \
    cp16(uA[buf] + (unsigned)(arow * 40 + acol) * 2,                                         \
         A + (size_t)r0_ * K + k0_ + acol, r0_ < M);                                         \
    cp16(uA[buf] + (unsigned)((arow + 64) * 40 + acol) * 2,                                  \
         A + (size_t)(r0_ + 64) * K + k0_ + acol, (r0_ + 64) < M);                           \
    cp16(uB[buf] + (unsigned)(arow * 40 + acol) * 2,                                         \
         B + (size_t)(n0 + arow) * K + k0_ + acol, true);                                    \
} while (0)

    LOADC(0, 0);
    cp_commit();

    for (int kt = 0; kt < nk; kt++) {
        int s = kt & 1, o = s ^ 1;
        if (kt + 1 < nk) {
            LOADC(kt + 1, o);
            cp_commit();
            cp_wait<1>();
        } else {
            cp_wait<0>();
        }
        __syncthreads();

        uint32_t uAb = uA[s], uBb = uB[s];
#pragma unroll
        for (int ks = 0; ks < 32; ks += 16) {
            uint32_t af[2][4], bf[4][2];
#pragma unroll
            for (int mt = 0; mt < 2; mt++) {
                int row = wm + mt * 16 + (lane & 15);
                int col = ks + ((lane >> 4) << 3);
                uint32_t addr = uAb + (unsigned)(row * 40 + col) * 2;
                asm volatile("ldmatrix.sync.aligned.m8n8.x4.shared.b16 {%0,%1,%2,%3}, [%4];"
                             : "=r"(af[mt][0]), "=r"(af[mt][1]), "=r"(af[mt][2]), "=r"(af[mt][3])
                             : "r"(addr));
            }
#pragma unroll
            for (int nt = 0; nt < 4; nt++) {
                int row = wn + nt * 8 + (lane & 7);
                int col = ks + (((lane >> 3) & 1) << 3);
                uint32_t addr = uBb + (unsigned)(row * 40 + col) * 2;
                asm volatile("ldmatrix.sync.aligned.m8n8.x2.shared.b16 {%0,%1}, [%2];"
                             : "=r"(bf[nt][0]), "=r"(bf[nt][1]) : "r"(addr));
            }
#pragma unroll
            for (int nt = 0; nt < 4; nt++)
#pragma unroll
                for (int mt = 0; mt < 2; mt++)
                    asm volatile(
                        "mma.sync.aligned.m16n8k16.row.col.f32.f16.f16.f32 "
                        "{%0,%1,%2,%3}, {%4,%5,%6,%7}, {%8,%9}, {%0,%1,%2,%3};"
                        : "+f"(acc[mt][nt][0]), "+f"(acc[mt][nt][1]),
                          "+f"(acc[mt][nt][2]), "+f"(acc[mt][nt][3])
                        : "r"(af[mt][0]), "r"(af[mt][1]), "r"(af[mt][2]), "r"(af[mt][3]),
                          "r"(bf[nt][0]), "r"(bf[nt][1]));
        }
        __syncthreads();
    }
#undef LOADC

#pragma unroll
    for (int mt = 0; mt < 2; mt++) {
        int r0 = m0 + wm + mt * 16 + (lane >> 2);
#pragma unroll
        for (int nt = 0; nt < 4; nt++) {
            int c = n0 + wn + nt * 8 + 2 * (lane & 3);
            float bx = bias ? bias[c] : 0.f;
            float by = bias ? bias[c + 1] : 0.f;
#pragma unroll
            for (int h = 0; h < 2; h++) {
                int row = r0 + h * 8;
                if (row >= M) continue;
                float vx = acc[mt][nt][h * 2 + 0] + bx;
                float vy = acc[mt][nt][h * 2 + 1] + by;
                if (WRITEF || ACCUM) {
                    float* cp = C + (size_t)row * Nout + c;
                    if (ACCUM) { vx += cp[0]; vy += cp[1]; }
                    cp[0] = vx; cp[1] = vy;
                }
                if (WRITEH) {
                    __half* hp = CH + (size_t)row * Nout + c;
                    hp[0] = __float2half(vx); hp[1] = __float2half(vy);
                }
            }
        }
    }
}

// ---------------- weight preprocessing ----------------
__global__ void trans_qkv_h(const float* __restrict__ Wq, const float* __restrict__ Wk,
                            const float* __restrict__ Wv,
                            const float* __restrict__ bq, const float* __restrict__ bk,
                            const float* __restrict__ bv)
{
    int i = blockIdx.x * blockDim.x + threadIdx.x;
    if (i < NBB * NTT * DD * DD) {
        int bt = i / (DD * DD);
        int b = bt / NTT, t = bt % NTT;
        int r  = i % (DD * DD);
        int n = r / DD, k = r % DD;
        size_t in = (size_t)bt * DD * DD + (size_t)k * DD + n;
        size_t o0 = (((size_t)(b * 3 + 0) * NTT + t)) * DD * DD + r;
        size_t o1 = (((size_t)(b * 3 + 1) * NTT + t)) * DD * DD + r;
        size_t o2 = (((size_t)(b * 3 + 2) * NTT + t)) * DD * DD + r;
        g_WQKVTH[o0] = __float2half(Wq[in]);
        g_WQKVTH[o1] = __float2half(Wk[in]);
        g_WQKVTH[o2] = __float2half(Wv[in]);
    } else {
        int j = i - NBB * NTT * DD * DD;
        if (j < NBB * NTT * DD) {
            int bt = j / DD, c = j % DD;
            int b = bt / NTT, t = bt % NTT;
            g_BQKV[(((size_t)(b * 3 + 0) * NTT + t)) * DD + c] = bq[j];
            g_BQKV[(((size_t)(b * 3 + 1) * NTT + t)) * DD + c] = bk[j];
            g_BQKV[(((size_t)(b * 3 + 2) * NTT + t)) * DD + c] = bv[j];
        }
    }
}

__global__ void wsumT_h(const float* __restrict__ Ws, const float* __restrict__ bs)
{
    int i = blockIdx.x * blockDim.x + threadIdx.x;
    if (i < NBB * DD * DD) {
        int b = i / (DD * DD), r = i % (DD * DD);
        int n = r / DD, k = r % DD;
        float s = 0.f;
#pragma unroll
        for (int t = 0; t < NTT; t++)
            s += Ws[((size_t)b * NTT + t) * DD * DD + (size_t)k * DD + n];
        g_WSUMTH[i] = __float2half(s);
    } else {
        int j = i - NBB * DD * DD;
        if (j < NBB * DD) {
            int b = j / DD, c = j % DD;
            float s = 0.f;
#pragma unroll
            for (int t = 0; t < NTT; t++) s += bs[((size_t)b * NTT + t) * DD + c];
            g_BSUM[j] = s;
        }
    }
}

__global__ void werT_h(const float* __restrict__ We)
{
    int i = blockIdx.x * blockDim.x + threadIdx.x;
    if (i >= NBB * DD * NTT * EHH) return;
    int b = i / (DD * NTT * EHH);
    int r = i % (DD * NTT * EHH);
    int n = r / (NTT * EHH);
    int tj = r % (NTT * EHH);
    g_WERTH[i] = __float2half(We[((size_t)b * NTT * EHH + tj) * DD + n]);
}

__global__ void wqwb_h(const float* __restrict__ We)
{
    int i = blockIdx.x * blockDim.x + threadIdx.x;
    if (i >= NBB * NTT * 64 * DD) return;
    int bt = i / (64 * DD);
    int r  = i % (64 * DD);
    int j = r / DD, k = r % DD;
    g_WQWBH[i] = (j < EHH) ? __float2half(We[((size_t)bt * EHH + j) * DD + k]) : __float2half(0.f);
}

__global__ void w1T_h(const float* __restrict__ W1)
{
    int i = blockIdx.x * blockDim.x + threadIdx.x;
    if (i >= 64 * DD) return;
    int n = i / DD, k = i % DD;
    float v = (n < EHH) ? W1[(size_t)k * EHH + n]
                        : W1[(size_t)(DD + k) * EHH + (n - EHH)];
    g_W1TH[i] = __float2half(v);
}

__global__ void conv_X(const float* __restrict__ x)
{
    size_t i = (size_t)blockIdx.x * blockDim.x + threadIdx.x;
    if (i < NND_C) g_HH[i] = __float2half(x[i]);
}

// ---------------- CSR build (node-keyed, all 9 types) ----------------
__global__ void csr_count(const int* __restrict__ EI)
{
    int i = blockIdx.x * blockDim.x + threadIdx.x;
    if (i >= NE9) return;
    int t = i / EE, e = i - t * EE;
    int dst = EI[((size_t)t * 2 + 1) * EE + e];
    atomicAdd(&g_CNT[dst], 1);
}

__global__ void __launch_bounds__(1024) csr_scan()
{
    __shared__ int sm[1024];
    int tid = threadIdx.x;
    const int CH = (NN + 1023) / 1024;
    int lo = tid * CH, hi = lo + CH < NN ? lo + CH : NN;
    int s = 0;
    for (int i = lo; i < hi; i++) s += g_CNT[i];
    sm[tid] = s;
    __syncthreads();
    for (int off = 1; off < 1024; off <<= 1) {
        int v = (tid >= off) ? sm[tid - off] : 0;
        __syncthreads();
        sm[tid] += v;
        __syncthreads();
    }
    int run = (tid > 0) ? sm[tid - 1] : 0;
    for (int i = lo; i < hi; i++) {
        int c = g_CNT[i];
        g_CNT[i] = run;
        g_POS[i] = run;
        run += c;
    }
    if (tid == 1023) g_CNT[NN] = sm[1023];
}

__global__ void csr_fill(const int* __restrict__ EI)
{
    int i = blockIdx.x * blockDim.x + threadIdx.x;
    if (i >= NE9) return;
    int t = i / EE, e = i - t * EE;
    int dst = EI[((size_t)t * 2 + 1) * EE + e];
    int src = EI[((size_t)t * 2 + 0) * EE + e];
    int p = atomicAdd(&g_POS[dst], 1);
    g_CSRE[p] = i;
    g_CSRS[p] = src;
    g_CSRTD[p] = (t << 16) | dst;
}

// reorder NEA into CSR order (one-time; sequential writes, gathered reads)
__global__ void nea_reorder()
{
    long i = (long)blockIdx.x * blockDim.x + threadIdx.x;
    if (i >= (long)NE9 * EHH) return;
    int idx = (int)(i >> 5);
    int lane = (int)(i & 31);
    int pe = g_CSRE[idx];
    g_NEAC[(size_t)idx * EHH + lane] = g_NEAH[(size_t)pe * EHH + lane];
}

// ---------------- edge MLP (reads packed XSD) ----------------
__global__ void edge_mlp(const int* __restrict__ EI, const float* __restrict__ EA,
                         const float* __restrict__ W1, const float* __restrict__ b1,
                         const float* __restrict__ W2, const float* __restrict__ b2)
{
    __shared__ float sW1e[EDIN * EHH];
    __shared__ float sW2[EHH * EHH];
    __shared__ float sb1[EHH], sb2[EHH];
    int tid = threadIdx.x;
    for (int i = tid; i < EDIN * EHH; i += blockDim.x) sW1e[i] = W1[640 * EHH + i];
    for (int i = tid; i < EHH * EHH; i += blockDim.x)  sW2[i]  = W2[i];
    if (tid < EHH) { sb1[tid] = b1[tid]; sb2[tid] = b2[tid]; }
    __syncthreads();

    long w = (long)blockIdx.x * (blockDim.x / 32) + tid / 32;
    int lane = tid & 31;
    if (w >= (long)NE9) return;
    int t = (int)(w / EE);
    int e = (int)(w % EE);
    int src = EI[((size_t)t * 2 + 0) * EE + e];
    int dst = EI[((size_t)t * 2 + 1) * EE + e];

    float eav = 0.f;
    if (lane < EDIN) eav = EA[((size_t)t * EE + e) * EDIN + lane];

    float h = sb1[lane] + g_XSD[(size_t)src * 64 + lane] + g_XSD[(size_t)dst * 64 + 32 + lane];
#pragma unroll
    for (int i = 0; i < EDIN; i++)
        h += __shfl_sync(0xffffffffu, eav, i) * sW1e[i * EHH + lane];
    h = h > 0.f ? h : 0.01f * h;

    float o = sb2[lane];
#pragma unroll
    for (int i = 0; i < EHH; i++)
        o += __shfl_sync(0xffffffffu, h, i) * sW2[i * EHH + lane];

    g_NEAH[((size_t)t * EE + e) * EHH + lane] = __float2half(o);
}

// ---------------- attention (CSR-ordered, no-amax softmax) ----------------
__global__ void att_pass1()
{
    long idx = (long)blockIdx.x * 8 + (threadIdx.x >> 5);
    int lane = threadIdx.x & 31;
    if (idx >= NE9) return;
    int src = g_CSRS[idx];
    int td  = g_CSRTD[idx];
    int t = td >> 16, dst = td & 0xFFFF;
    const __half2* q2 = (const __half2*)(g_QKVH + ((size_t)t * NN + dst) * DD);
    const __half2* k2 = (const __half2*)(g_QKVH + (size_t)NTT * NND_C + ((size_t)t * NN + src) * DD);
    float s = g_QW[((size_t)t * NN + dst) * 64 + lane]
            * __half2float(g_NEAC[(size_t)idx * EHH + lane]);
#pragma unroll
    for (int i = 0; i < 5; i++) {
        float2 qa = __half22float2(q2[lane + 32 * i]);
        float2 kb = __half22float2(k2[lane + 32 * i]);
        s += qa.x * kb.x + qa.y * kb.y;
    }
#pragma unroll
    for (int off = 16; off; off >>= 1) s += __shfl_xor_sync(0xffffffffu, s, off);
    if (lane == 0) {
        float ex = expf(s * 0.05590169943749474f);
        g_AL[idx] = ex;
        atomicAdd(&g_DEN[(size_t)t * NN + dst], ex);
    }
}

__global__ void __launch_bounds__(256) att_gather(const float* __restrict__ be_b)
{
    __shared__ float sW[8][NTT * EHH];
    __shared__ float sSW[8][NTT];
    __shared__ __align__(8) float sBE[NTT * DD];

    int tid = threadIdx.x;
    for (int j = tid; j < NTT * DD; j += 256) sBE[j] = be_b[j];

    int wrp = tid >> 5, lane = tid & 31;
    int node = blockIdx.x * 8 + wrp;
    for (int j = lane; j < NTT * EHH; j += 32) sW[wrp][j] = 0.f;
    if (lane < NTT) sSW[wrp][lane] = 0.f;
    __syncthreads();
    if (node >= NN) return;

    float2 acc[5];
    float2* accp = (float2*)(g_ACC + (size_t)node * DD);
#pragma unroll
    for (int i = 0; i < 5; i++) acc[i] = accp[lane + 32 * i];

    int start = g_CNT[node], end = g_CNT[node + 1];
    for (int idx = start; idx < end; idx++) {
        int src = g_CSRS[idx];
        int t   = g_CSRTD[idx] >> 16;
        float w = g_AL[idx] / (g_DEN[(size_t)t * NN + node] + 1e-16f);
        const __half2* v2 = (const __half2*)(g_QKVH + (size_t)2 * NTT * NND_C
                                             + ((size_t)t * NN + src) * DD);
#pragma unroll
        for (int i = 0; i < 5; i++) {
            float2 vv = __half22float2(v2[lane + 32 * i]);
            acc[i].x += w * vv.x;
            acc[i].y += w * vv.y;
        }
        sW[wrp][t * EHH + lane] += w * __half2float(g_NEAC[(size_t)idx * EHH + lane]);
        if (lane == 0) sSW[wrp][t] += w;
    }
    __syncwarp();

    const float2* sBE2 = (const float2*)sBE;
#pragma unroll
    for (int t = 0; t < NTT; t++) {
        float swt = sSW[wrp][t];
        if (swt != 0.f) {
#pragma unroll
            for (int i = 0; i < 5; i++) {
                float2 bb = sBE2[t * 160 + lane + 32 * i];
                acc[i].x += swt * bb.x;
                acc[i].y += swt * bb.y;
            }
        }
    }

#pragma unroll
    for (int i = 0; i < 5; i++) accp[lane + 32 * i] = acc[i];
    __half* wn = g_WNEAH + (size_t)node * (NTT * EHH);
#pragma unroll
    for (int t = 0; t < NTT; t++) wn[t * EHH + lane] = __float2half(sW[wrp][t * EHH + lane]);
}

// ---------------- norm / residual / pooling ----------------
__global__ void count_nodes(const int* __restrict__ batch)
{
    int i = blockIdx.x * blockDim.x + threadIdx.x;
    if (i < NN) atomicAdd(&g_GC[batch[i]], 1);
}

__global__ void gstats(const int* __restrict__ batch)
{
    int w = blockIdx.x * (blockDim.x / 32) + threadIdx.x / 32;
    int lane = threadIdx.x & 31;
    if (w >= NN) return;
    const float* a = g_ACC + (size_t)w * DD;
    float s1 = 0.f, s2 = 0.f;
#pragma unroll
    for (int c = lane; c < DD; c += 32) {
        float v = a[c] * (1.f / 9.f);
        v = v > 0.f ? v : 0.01f * v;
        s1 += v; s2 += v * v;
    }
#pragma unroll
    for (int off = 16; off; off >>= 1) {
        s1 += __shfl_xor_sync(0xffffffffu, s1, off);
        s2 += __shfl_xor_sync(0xffffffffu, s2, off);
    }
    if (lane == 0) {
        int g = batch[w];
        atomicAdd(&g_GS[g], s1);
        atomicAdd(&g_GQ[g], s2);
    }
}

__global__ void gfinal()
{
    int g = blockIdx.x * blockDim.x + threadIdx.x;
    if (g >= GG) return;
    float cnt  = (float)g_GC[g];
    float norm = fmaxf(cnt, 1.f) * (float)DD;
    float mean = g_GS[g] / norm;
    float var  = fmaxf(g_GQ[g] / norm - mean * mean, 0.f);
    g_MEAN[g] = mean;
    g_RSTD[g] = rsqrtf(var + 1e-5f);
}

__device__ __forceinline__ unsigned fkey(float f)
{
    unsigned u = __float_as_uint(f);
    return (u & 0x80000000u) ? ~u : (u | 0x80000000u);
}
__device__ __forceinline__ float funkey(unsigned u)
{
    return (u & 0x80000000u) ? __uint_as_float(u & 0x7FFFFFFFu) : __uint_as_float(~u);
}

template<bool WRITEH, bool MAXRED>
__global__ void hupdate(const int* __restrict__ batch,
                        const float* __restrict__ gamma, const float* __restrict__ beta)
{
    size_t i = (size_t)blockIdx.x * blockDim.x + threadIdx.x;
    if (i >= NND_C) return;
    int node = (int)(i / DD), c = (int)(i % DD);
    int g = batch[node];
    float v = g_ACC[i] * (1.f / 9.f);
    v = v > 0.f ? v : 0.01f * v;
    float xn = (v - g_MEAN[g]) * g_RSTD[g] * gamma[c] + beta[c];
    float hn = 0.5f * (g_H[i] + xn);
    g_H[i] = hn;
    if (WRITEH) g_HH[i] = __float2half(hn);
    if (MAXRED) atomicMax(&g_OUTU[(size_t)g * DD + c], fkey(hn));
}

__global__ void finalize(float* __restrict__ out)
{
    int i = blockIdx.x * blockDim.x + threadIdx.x;
    if (i < GG * DD) out[i] = funkey(g_OUTU[i]);
}

// ---------------- host orchestration ----------------
extern "C" void kernel_launch(void* const* d_in, const int* in_sizes, int n_in,
                              void* d_out, int out_size)
{
    const float* x     = (const float*)d_in[0];
    const int*   batch = (const int*)d_in[1];
    const int*   EI    = (const int*)d_in[2];
    const float* EA    = (const float*)d_in[3];
    const float* W1    = (const float*)d_in[4];
    const float* b1    = (const float*)d_in[5];
    const float* W2    = (const float*)d_in[6];
    const float* b2    = (const float*)d_in[7];
    const float* Wq    = (const float*)d_in[8];
    const float* bq    = (const float*)d_in[9];
    const float* Wk    = (const float*)d_in[10];
    const float* bk    = (const float*)d_in[11];
    const float* Wv    = (const float*)d_in[12];
    const float* bv    = (const float*)d_in[13];
    const float* We    = (const float*)d_in[14];
    const float* be    = (const float*)d_in[15];
    const float* Ws    = (const float*)d_in[16];
    const float* bs    = (const float*)d_in[17];
    const float* gamma = (const float*)d_in[18];
    const float* beta  = (const float*)d_in[19];
    float* out = (float*)d_out;

    float *pQW, *pACC, *pH, *pXSD, *pGS, *pGQ, *pBSUM, *pBQKV, *pDEN;
    __half *pQKVH, *pHH, *pWNEAH, *pWQKVTH, *pWSUMTH, *pWERTH, *pWQWBH, *pW1TH;
    int *pGC, *pCNT;
    unsigned *pOUTU;
    cudaGetSymbolAddress((void**)&pXSD,     g_XSD);
    cudaGetSymbolAddress((void**)&pQKVH,    g_QKVH);
    cudaGetSymbolAddress((void**)&pQW,      g_QW);
    cudaGetSymbolAddress((void**)&pWNEAH,   g_WNEAH);
    cudaGetSymbolAddress((void**)&pACC,     g_ACC);
    cudaGetSymbolAddress((void**)&pH,       g_H);
    cudaGetSymbolAddress((void**)&pHH,      g_HH);
    cudaGetSymbolAddress((void**)&pGS,      g_GS);
    cudaGetSymbolAddress((void**)&pGQ,      g_GQ);
    cudaGetSymbolAddress((void**)&pGC,      g_GC);
    cudaGetSymbolAddress((void**)&pCNT,     g_CNT);
    cudaGetSymbolAddress((void**)&pBSUM,    g_BSUM);
    cudaGetSymbolAddress((void**)&pBQKV,    g_BQKV);
    cudaGetSymbolAddress((void**)&pDEN,     g_DEN);
    cudaGetSymbolAddress((void**)&pWQKVTH,  g_WQKVTH);
    cudaGetSymbolAddress((void**)&pWSUMTH,  g_WSUMTH);
    cudaGetSymbolAddress((void**)&pWERTH,   g_WERTH);
    cudaGetSymbolAddress((void**)&pWQWBH,   g_WQWBH);
    cudaGetSymbolAddress((void**)&pW1TH,    g_W1TH);
    cudaGetSymbolAddress((void**)&pOUTU,    g_OUTU);

    const int MT = (NN + 127) / 128;        // 391
    const long NND = (long)NN * DD;

    // ---- preprocessing ----
    cudaMemsetAsync(pGC, 0, GG * sizeof(int));
    cudaMemsetAsync(pOUTU, 0, (size_t)GG * DD * sizeof(unsigned));
    count_nodes<<<(NN + 255) / 256, 256>>>(batch);

    trans_qkv_h<<<(NBB * NTT * DD * DD + NBB * NTT * DD + 255) / 256, 256>>>(Wq, Wk, Wv, bq, bk, bv);
    wsumT_h<<<(NBB * DD * DD + NBB * DD + 255) / 256, 256>>>(Ws, bs);
    werT_h<<<(NBB * DD * NTT * EHH + 255) / 256, 256>>>(We);
    wqwb_h<<<(NBB * NTT * 64 * DD + 255) / 256, 256>>>(We);
    w1T_h<<<(64 * DD + 255) / 256, 256>>>(W1);

    cudaMemsetAsync(pCNT, 0, (NN + 1) * sizeof(int));
    csr_count<<<(NE9 + 255) / 256, 256>>>(EI);
    csr_scan<<<1, 1024>>>();
    csr_fill<<<(NE9 + 255) / 256, 256>>>(EI);

    cudaMemcpyAsync(pH, x, NND * sizeof(float), cudaMemcpyDeviceToDevice);
    conv_X<<<(unsigned)((NND + 255) / 256), 256>>>(x);

    // XSD = HH @ [W1src|W1dst]^T
    hgemm<false, true, false><<<dim3(1, MT, 1), 256>>>(
        pHH, pW1TH, nullptr, pXSD, nullptr, NN, DD, 64, 0, 0, 0, 0);
    edge_mlp<<<(NE9 + 7) / 8, 256>>>(EI, EA, W1, b1, W2, b2);
    nea_reorder<<<(unsigned)(((long)NE9 * EHH + 255) / 256), 256>>>();

    for (int b = 0; b < NBB; b++) {
        // skip (folded): ACC = HH @ WSUM_b^T + BSUM_b
        hgemm<false, true, false><<<dim3(5, MT, 1), 256>>>(
            pHH, pWSUMTH + (size_t)b * DD * DD, pBSUM + (size_t)b * DD, pACC, nullptr,
            NN, DD, DD, 0, 0, 0, 0);

        // fused Q/K/V (z = 27), fp16 packed output
        hgemm<false, false, true><<<dim3(5, MT, 3 * NTT), 256>>>(
            pHH, pWQKVTH + (size_t)b * 3 * NTT * DD * DD, pBQKV + (size_t)b * 3 * NTT * DD,
            nullptr, pQKVH,
            NN, DD, DD, 0, (long)DD * DD, NND, DD);

        // QW_t = Q_t @ We_t^T (Nout=64, z=9)
        hgemm<false, true, false><<<dim3(1, MT, NTT), 256>>>(
            pQKVH, pWQWBH + (size_t)b * NTT * 64 * DD, nullptr, pQW, nullptr,
            NN, DD, 64, NND, (long)64 * DD, (long)NN * 64, 0);

        cudaMemsetAsync(pDEN, 0, (size_t)NTT * NN * sizeof(float));
        att_pass1<<<(NE9 + 7) / 8, 256>>>();
        att_gather<<<(NN + 7) / 8, 256>>>(be + (size_t)b * NTT * DD);

        // ACC += WNEA @ [stacked We] (K=288)
        hgemm<true, true, false><<<dim3(5, MT, 1), 256>>>(
            pWNEAH, pWERTH + (size_t)b * DD * NTT * EHH, nullptr, pACC, nullptr,
            NN, NTT * EHH, DD, 0, 0, 0, 0);

        cudaMemsetAsync(pGS, 0, GG * sizeof(float));
        cudaMemsetAsync(pGQ, 0, GG * sizeof(float));
        gstats<<<(NN + 7) / 8, 256>>>(batch);
        gfinal<<<1, 256>>>();
        if (b + 1 < NBB)
            hupdate<true, false><<<(unsigned)((NND + 255) / 256), 256>>>(
                batch, gamma + (size_t)b * DD, beta + (size_t)b * DD);
        else
            hupdate<false, true><<<(unsigned)((NND + 255) / 256), 256>>>(
                batch, gamma + (size_t)b * DD, beta + (size_t)b * DD);
    }

    finalize<<<(GG * DD + 255) / 256, 256>>>(out);
}

// round 17
// speedup vs baseline: 1.0561x; 1.0117x over previous
#include <cuda_runtime.h>
#include <cuda_fp16.h>
#include <math.h>
#include <cstdint>

#define NN   50000
#define EE   150000
#define GG   200
#define DD   320
#define EDIN 15
#define EHH  32
#define NBB  3
#define NTT  9
#define NE9  (NTT * EE)
#define NND_C ((size_t)NN * DD)

// ---------------- scratch (static device globals; allocation-free) ----------------
__device__ __half g_NEAH[NTT * EE * EHH];
__device__ float  g_XSD[NN * 64];              // packed [node][0:32]=XS, [32:64]=XD
__device__ __half g_QKVH[3 * NTT * NN * DD];   // [qkv][t][N][D]
__device__ float  g_QW[NTT * NN * 64];
__device__ __half g_WNEAH[NN * NTT * EHH];
__device__ float  g_ACC[NN * DD];
__device__ float  g_H[NN * DD];
__device__ __half g_HH[NN * DD];
__device__ float  g_AL[NE9];                   // CSR-ordered exp(alpha)
__device__ float  g_DEN[NTT * NN];
// fp16 pre-transposed weights, B-operand layout [Nout][K] (K contiguous)
__device__ __half g_WQKVTH[NBB * 3 * NTT * DD * DD];  // [b][qkv][t][n][k]
__device__ float  g_BQKV[NBB * 3 * NTT * DD];
__device__ __half g_WSUMTH[NBB * DD * DD];
__device__ float  g_BSUM[NBB * DD];
__device__ __half g_WERTH[NBB * DD * (NTT * EHH)];  // [b][320][288]
__device__ __half g_WQWBH[NBB * NTT * 64 * DD];     // [bt][64][320], rows 32..63 zero
__device__ __half g_W1TH[64 * DD];                  // rows 0-31: W1src^T, 32-63: W1dst^T
// CSR (node-keyed over all 9 types)
__device__ int   g_CNT[NN + 1];
__device__ int   g_POS[NN];
__device__ int   g_CSRE[NE9];
__device__ int   g_CSRS[NE9];
__device__ int   g_CSRD[NE9];
__device__ float g_GS[GG];
__device__ float g_GQ[GG];
__device__ int   g_GC[GG];
__device__ float g_MEAN[GG];
__device__ float g_RSTD[GG];
__device__ unsigned g_OUTU[GG * DD];

// ---------------- helpers ----------------
__device__ __forceinline__ uint32_t smem_u32(const void* p)
{
    uint32_t a;
    asm("{ .reg .u64 t; cvta.to.shared.u64 t, %1; cvt.u32.u64 %0, t; }" : "=r"(a) : "l"(p));
    return a;
}

__device__ __forceinline__ void cp16(unsigned dst, const void* src, bool p)
{
    asm volatile("cp.async.cg.shared.global [%0], [%1], 16, %2;"
                 :: "r"(dst), "l"(src), "r"(p ? 16 : 0));
}
__device__ __forceinline__ void cp_commit() { asm volatile("cp.async.commit_group;"); }
template<int N> __device__ __forceinline__ void cp_wait() { asm volatile("cp.async.wait_group %0;" :: "n"(N)); }

// ---------------- FP16 tensor-core GEMM (m16n8k16), 3-stage cp.async pipeline ----------
// C[M,Nout] = A[M,K](fp16 row-major) @ B^T, B stored [Nout][K] fp16.
// BM=128, BN=64, BK=32; 256 threads, 8 warps 4(m)x2(n), warp tile 32x32.
template<bool ACCUM, bool WRITEF, bool WRITEH>
__global__ void __launch_bounds__(256) hgemm(
    const __half* __restrict__ A, const __half* __restrict__ B,
    const float* __restrict__ bias, float* __restrict__ C, __half* __restrict__ CH,
    int M, int K, int Nout,
    long aZ, long bZ, long cZ, long biasZ)
{
    __shared__ __align__(16) __half As[3][128 * 40];
    __shared__ __align__(16) __half Bs[3][64 * 40];

    const int z = blockIdx.z;
    A += (size_t)z * aZ; B += (size_t)z * bZ;
    if (WRITEF || ACCUM) C += (size_t)z * cZ;
    if (WRITEH) CH += (size_t)z * cZ;
    if (bias) bias += (size_t)z * biasZ;

    const int tid  = threadIdx.x;
    const int lane = tid & 31;
    const int wid  = tid >> 5;
    const int wm   = (wid & 3) * 32;
    const int wn   = (wid >> 2) * 32;
    const int m0 = blockIdx.y * 128;
    const int n0 = blockIdx.x * 64;

    uint32_t uA[3] = { smem_u32(As[0]), smem_u32(As[1]), smem_u32(As[2]) };
    uint32_t uB[3] = { smem_u32(Bs[0]), smem_u32(Bs[1]), smem_u32(Bs[2]) };

    const int arow = tid >> 2;
    const int acol = (tid & 3) * 8;

    float acc[2][4][4];
#pragma unroll
    for (int mt = 0; mt < 2; mt++)
#pragma unroll
        for (int nt = 0; nt < 4; nt++)
#pragma unroll
            for (int i = 0; i < 4; i++) acc[mt][nt][i] = 0.f;

    const int nk = K / 32;

#define LOADC(c, buf) do {                                                                   \
    int k0_ = (c) * 32;                                                                      \
    int r0_ = m0 + arow;                                                                     \
    cp16(uA[buf] + (unsigned)(arow * 40 + acol) * 2,                                         \
         A + (size_t)r0_ * K + k0_ + acol, r0_ < M);                                         \
    cp16(uA[buf] + (unsigned)((arow + 64) * 40 + acol) * 2,                                  \
         A + (size_t)(r0_ + 64) * K + k0_ + acol, (r0_ + 64) < M);                           \
    cp16(uB[buf] + (unsigned)(arow * 40 + acol) * 2,                                         \
         B + (size_t)(n0 + arow) * K + k0_ + acol, true);                                    \
} while (0)

    // prologue: stages 0 and 1 in flight
    LOADC(0, 0);
    cp_commit();
    if (nk > 1) LOADC(1, 1);
    cp_commit();

    for (int kt = 0; kt < nk; kt++) {
        int s = kt % 3;
        if (kt + 2 < nk) LOADC(kt + 2, (kt + 2) % 3);
        cp_commit();          // may be empty; keeps group arithmetic uniform
        cp_wait<2>();         // stage kt's group is complete
        __syncthreads();

        uint32_t uAb = uA[s], uBb = uB[s];
#pragma unroll
        for (int ks = 0; ks < 32; ks += 16) {
            uint32_t af[2][4], bf[4][2];
#pragma unroll
            for (int mt = 0; mt < 2; mt++) {
                int row = wm + mt * 16 + (lane & 15);
                int col = ks + ((lane >> 4) << 3);
                uint32_t addr = uAb + (unsigned)(row * 40 + col) * 2;
                asm volatile("ldmatrix.sync.aligned.m8n8.x4.shared.b16 {%0,%1,%2,%3}, [%4];"
                             : "=r"(af[mt][0]), "=r"(af[mt][1]), "=r"(af[mt][2]), "=r"(af[mt][3])
                             : "r"(addr));
            }
#pragma unroll
            for (int nt = 0; nt < 4; nt++) {
                int row = wn + nt * 8 + (lane & 7);
                int col = ks + (((lane >> 3) & 1) << 3);
                uint32_t addr = uBb + (unsigned)(row * 40 + col) * 2;
                asm volatile("ldmatrix.sync.aligned.m8n8.x2.shared.b16 {%0,%1}, [%2];"
                             : "=r"(bf[nt][0]), "=r"(bf[nt][1]) : "r"(addr));
            }
#pragma unroll
            for (int nt = 0; nt < 4; nt++)
#pragma unroll
                for (int mt = 0; mt < 2; mt++)
                    asm volatile(
                        "mma.sync.aligned.m16n8k16.row.col.f32.f16.f16.f32 "
                        "{%0,%1,%2,%3}, {%4,%5,%6,%7}, {%8,%9}, {%0,%1,%2,%3};"
                        : "+f"(acc[mt][nt][0]), "+f"(acc[mt][nt][1]),
                          "+f"(acc[mt][nt][2]), "+f"(acc[mt][nt][3])
                        : "r"(af[mt][0]), "r"(af[mt][1]), "r"(af[mt][2]), "r"(af[mt][3]),
                          "r"(bf[nt][0]), "r"(bf[nt][1]));
        }
        __syncthreads();
    }
#undef LOADC

#pragma unroll
    for (int mt = 0; mt < 2; mt++) {
        int r0 = m0 + wm + mt * 16 + (lane >> 2);
#pragma unroll
        for (int nt = 0; nt < 4; nt++) {
            int c = n0 + wn + nt * 8 + 2 * (lane & 3);
            float bx = bias ? bias[c] : 0.f;
            float by = bias ? bias[c + 1] : 0.f;
#pragma unroll
            for (int h = 0; h < 2; h++) {
                int row = r0 + h * 8;
                if (row >= M) continue;
                float vx = acc[mt][nt][h * 2 + 0] + bx;
                float vy = acc[mt][nt][h * 2 + 1] + by;
                if (WRITEF || ACCUM) {
                    float* cp = C + (size_t)row * Nout + c;
                    if (ACCUM) { vx += cp[0]; vy += cp[1]; }
                    cp[0] = vx; cp[1] = vy;
                }
                if (WRITEH) {
                    __half* hp = CH + (size_t)row * Nout + c;
                    hp[0] = __float2half(vx); hp[1] = __float2half(vy);
                }
            }
        }
    }
}

// ---------------- weight preprocessing ----------------
__global__ void trans_qkv_h(const float* __restrict__ Wq, const float* __restrict__ Wk,
                            const float* __restrict__ Wv,
                            const float* __restrict__ bq, const float* __restrict__ bk,
                            const float* __restrict__ bv)
{
    int i = blockIdx.x * blockDim.x + threadIdx.x;
    if (i < NBB * NTT * DD * DD) {
        int bt = i / (DD * DD);
        int b = bt / NTT, t = bt % NTT;
        int r  = i % (DD * DD);
        int n = r / DD, k = r % DD;
        size_t in = (size_t)bt * DD * DD + (size_t)k * DD + n;
        size_t o0 = (((size_t)(b * 3 + 0) * NTT + t)) * DD * DD + r;
        size_t o1 = (((size_t)(b * 3 + 1) * NTT + t)) * DD * DD + r;
        size_t o2 = (((size_t)(b * 3 + 2) * NTT + t)) * DD * DD + r;
        g_WQKVTH[o0] = __float2half(Wq[in]);
        g_WQKVTH[o1] = __float2half(Wk[in]);
        g_WQKVTH[o2] = __float2half(Wv[in]);
    } else {
        int j = i - NBB * NTT * DD * DD;
        if (j < NBB * NTT * DD) {
            int bt = j / DD, c = j % DD;
            int b = bt / NTT, t = bt % NTT;
            g_BQKV[(((size_t)(b * 3 + 0) * NTT + t)) * DD + c] = bq[j];
            g_BQKV[(((size_t)(b * 3 + 1) * NTT + t)) * DD + c] = bk[j];
            g_BQKV[(((size_t)(b * 3 + 2) * NTT + t)) * DD + c] = bv[j];
        }
    }
}

__global__ void wsumT_h(const float* __restrict__ Ws, const float* __restrict__ bs)
{
    int i = blockIdx.x * blockDim.x + threadIdx.x;
    if (i < NBB * DD * DD) {
        int b = i / (DD * DD), r = i % (DD * DD);
        int n = r / DD, k = r % DD;
        float s = 0.f;
#pragma unroll
        for (int t = 0; t < NTT; t++)
            s += Ws[((size_t)b * NTT + t) * DD * DD + (size_t)k * DD + n];
        g_WSUMTH[i] = __float2half(s);
    } else {
        int j = i - NBB * DD * DD;
        if (j < NBB * DD) {
            int b = j / DD, c = j % DD;
            float s = 0.f;
#pragma unroll
            for (int t = 0; t < NTT; t++) s += bs[((size_t)b * NTT + t) * DD + c];
            g_BSUM[j] = s;
        }
    }
}

__global__ void werT_h(const float* __restrict__ We)
{
    int i = blockIdx.x * blockDim.x + threadIdx.x;
    if (i >= NBB * DD * NTT * EHH) return;
    int b = i / (DD * NTT * EHH);
    int r = i % (DD * NTT * EHH);
    int n = r / (NTT * EHH);
    int tj = r % (NTT * EHH);
    g_WERTH[i] = __float2half(We[((size_t)b * NTT * EHH + tj) * DD + n]);
}

__global__ void wqwb_h(const float* __restrict__ We)
{
    int i = blockIdx.x * blockDim.x + threadIdx.x;
    if (i >= NBB * NTT * 64 * DD) return;
    int bt = i / (64 * DD);
    int r  = i % (64 * DD);
    int j = r / DD, k = r % DD;
    g_WQWBH[i] = (j < EHH) ? __float2half(We[((size_t)bt * EHH + j) * DD + k]) : __float2half(0.f);
}

__global__ void w1T_h(const float* __restrict__ W1)
{
    int i = blockIdx.x * blockDim.x + threadIdx.x;
    if (i >= 64 * DD) return;
    int n = i / DD, k = i % DD;
    float v = (n < EHH) ? W1[(size_t)k * EHH + n]
                        : W1[(size_t)(DD + k) * EHH + (n - EHH)];
    g_W1TH[i] = __float2half(v);
}

__global__ void conv_X(const float* __restrict__ x)
{
    size_t i = (size_t)blockIdx.x * blockDim.x + threadIdx.x;
    if (i < NND_C) g_HH[i] = __float2half(x[i]);
}

// ---------------- CSR build (node-keyed, all 9 types) ----------------
__global__ void csr_count(const int* __restrict__ EI)
{
    int i = blockIdx.x * blockDim.x + threadIdx.x;
    if (i >= NE9) return;
    int t = i / EE, e = i - t * EE;
    int dst = EI[((size_t)t * 2 + 1) * EE + e];
    atomicAdd(&g_CNT[dst], 1);
}

__global__ void __launch_bounds__(1024) csr_scan()
{
    __shared__ int sm[1024];
    int tid = threadIdx.x;
    const int CH = (NN + 1023) / 1024;
    int lo = tid * CH, hi = lo + CH < NN ? lo + CH : NN;
    int s = 0;
    for (int i = lo; i < hi; i++) s += g_CNT[i];
    sm[tid] = s;
    __syncthreads();
    for (int off = 1; off < 1024; off <<= 1) {
        int v = (tid >= off) ? sm[tid - off] : 0;
        __syncthreads();
        sm[tid] += v;
        __syncthreads();
    }
    int run = (tid > 0) ? sm[tid - 1] : 0;
    for (int i = lo; i < hi; i++) {
        int c = g_CNT[i];
        g_CNT[i] = run;
        g_POS[i] = run;
        run += c;
    }
    if (tid == 1023) g_CNT[NN] = sm[1023];
}

__global__ void csr_fill(const int* __restrict__ EI)
{
    int i = blockIdx.x * blockDim.x + threadIdx.x;
    if (i >= NE9) return;
    int t = i / EE, e = i - t * EE;
    int dst = EI[((size_t)t * 2 + 1) * EE + e];
    int src = EI[((size_t)t * 2 + 0) * EE + e];
    int p = atomicAdd(&g_POS[dst], 1);
    g_CSRE[p] = i;
    g_CSRS[p] = src;
    g_CSRD[p] = dst;
}

// ---------------- edge MLP (reads packed XSD) ----------------
__global__ void edge_mlp(const int* __restrict__ EI, const float* __restrict__ EA,
                         const float* __restrict__ W1, const float* __restrict__ b1,
                         const float* __restrict__ W2, const float* __restrict__ b2)
{
    __shared__ float sW1e[EDIN * EHH];
    __shared__ float sW2[EHH * EHH];
    __shared__ float sb1[EHH], sb2[EHH];
    int tid = threadIdx.x;
    for (int i = tid; i < EDIN * EHH; i += blockDim.x) sW1e[i] = W1[640 * EHH + i];
    for (int i = tid; i < EHH * EHH; i += blockDim.x)  sW2[i]  = W2[i];
    if (tid < EHH) { sb1[tid] = b1[tid]; sb2[tid] = b2[tid]; }
    __syncthreads();

    long w = (long)blockIdx.x * (blockDim.x / 32) + tid / 32;
    int lane = tid & 31;
    if (w >= (long)NE9) return;
    int t = (int)(w / EE);
    int e = (int)(w % EE);
    int src = EI[((size_t)t * 2 + 0) * EE + e];
    int dst = EI[((size_t)t * 2 + 1) * EE + e];

    float eav = 0.f;
    if (lane < EDIN) eav = EA[((size_t)t * EE + e) * EDIN + lane];

    float h = sb1[lane] + g_XSD[(size_t)src * 64 + lane] + g_XSD[(size_t)dst * 64 + 32 + lane];
#pragma unroll
    for (int i = 0; i < EDIN; i++)
        h += __shfl_sync(0xffffffffu, eav, i) * sW1e[i * EHH + lane];
    h = h > 0.f ? h : 0.01f * h;

    float o = sb2[lane];
#pragma unroll
    for (int i = 0; i < EHH; i++)
        o += __shfl_sync(0xffffffffu, h, i) * sW2[i * EHH + lane];

    g_NEAH[((size_t)t * EE + e) * EHH + lane] = __float2half(o);
}

// ---------------- attention (CSR-ordered pass1; no-amax softmax) ----------------
__global__ void att_pass1()
{
    long idx = (long)blockIdx.x * 8 + (threadIdx.x >> 5);
    int lane = threadIdx.x & 31;
    if (idx >= NE9) return;
    int pe  = g_CSRE[idx];
    int src = g_CSRS[idx];
    int dst = g_CSRD[idx];
    int t = pe / EE;
    const __half2* q2 = (const __half2*)(g_QKVH + ((size_t)t * NN + dst) * DD);
    const __half2* k2 = (const __half2*)(g_QKVH + (size_t)NTT * NND_C + ((size_t)t * NN + src) * DD);
    float s = g_QW[((size_t)t * NN + dst) * 64 + lane]
            * __half2float(g_NEAH[(size_t)pe * EHH + lane]);
#pragma unroll
    for (int i = 0; i < 5; i++) {
        float2 qa = __half22float2(q2[lane + 32 * i]);
        float2 kb = __half22float2(k2[lane + 32 * i]);
        s += qa.x * kb.x + qa.y * kb.y;
    }
#pragma unroll
    for (int off = 16; off; off >>= 1) s += __shfl_xor_sync(0xffffffffu, s, off);
    if (lane == 0) {
        float ex = expf(s * 0.05590169943749474f);
        g_AL[idx] = ex;
        atomicAdd(&g_DEN[(size_t)t * NN + dst], ex);
    }
}

__global__ void __launch_bounds__(256) att_gather(const float* __restrict__ be_b)
{
    __shared__ float sW[8][NTT * EHH];
    __shared__ float sSW[8][NTT];
    __shared__ __align__(8) float sBE[NTT * DD];

    int tid = threadIdx.x;
    for (int j = tid; j < NTT * DD; j += 256) sBE[j] = be_b[j];

    int wrp = tid >> 5, lane = tid & 31;
    int node = blockIdx.x * 8 + wrp;
    for (int j = lane; j < NTT * EHH; j += 32) sW[wrp][j] = 0.f;
    if (lane < NTT) sSW[wrp][lane] = 0.f;
    __syncthreads();
    if (node >= NN) return;

    float2 acc[5];
    float2* accp = (float2*)(g_ACC + (size_t)node * DD);
#pragma unroll
    for (int i = 0; i < 5; i++) acc[i] = accp[lane + 32 * i];

    int start = g_CNT[node], end = g_CNT[node + 1];
    for (int idx = start; idx < end; idx++) {
        int pe  = g_CSRE[idx];
        int src = g_CSRS[idx];
        int t = pe / EE;
        float w = g_AL[idx] / (g_DEN[(size_t)t * NN + node] + 1e-16f);
        const __half2* v2 = (const __half2*)(g_QKVH + (size_t)2 * NTT * NND_C
                                             + ((size_t)t * NN + src) * DD);
#pragma unroll
        for (int i = 0; i < 5; i++) {
            float2 vv = __half22float2(v2[lane + 32 * i]);
            acc[i].x += w * vv.x;
            acc[i].y += w * vv.y;
        }
        sW[wrp][t * EHH + lane] += w * __half2float(g_NEAH[(size_t)pe * EHH + lane]);
        if (lane == 0) sSW[wrp][t] += w;
    }
    __syncwarp();

    const float2* sBE2 = (const float2*)sBE;
#pragma unroll
    for (int t = 0; t < NTT; t++) {
        float swt = sSW[wrp][t];
        if (swt != 0.f) {
#pragma unroll
            for (int i = 0; i < 5; i++) {
                float2 bb = sBE2[t * 160 + lane + 32 * i];
                acc[i].x += swt * bb.x;
                acc[i].y += swt * bb.y;
            }
        }
    }

#pragma unroll
    for (int i = 0; i < 5; i++) accp[lane + 32 * i] = acc[i];
    __half* wn = g_WNEAH + (size_t)node * (NTT * EHH);
#pragma unroll
    for (int t = 0; t < NTT; t++) wn[t * EHH + lane] = __float2half(sW[wrp][t * EHH + lane]);
}

// ---------------- norm / residual / pooling ----------------
__global__ void count_nodes(const int* __restrict__ batch)
{
    int i = blockIdx.x * blockDim.x + threadIdx.x;
    if (i < NN) atomicAdd(&g_GC[batch[i]], 1);
}

__global__ void gstats(const int* __restrict__ batch)
{
    int w = blockIdx.x * (blockDim.x / 32) + threadIdx.x / 32;
    int lane = threadIdx.x & 31;
    if (w >= NN) return;
    const float* a = g_ACC + (size_t)w * DD;
    float s1 = 0.f, s2 = 0.f;
#pragma unroll
    for (int c = lane; c < DD; c += 32) {
        float v = a[c] * (1.f / 9.f);
        v = v > 0.f ? v : 0.01f * v;
        s1 += v; s2 += v * v;
    }
#pragma unroll
    for (int off = 16; off; off >>= 1) {
        s1 += __shfl_xor_sync(0xffffffffu, s1, off);
        s2 += __shfl_xor_sync(0xffffffffu, s2, off);
    }
    if (lane == 0) {
        int g = batch[w];
        atomicAdd(&g_GS[g], s1);
        atomicAdd(&g_GQ[g], s2);
    }
}

__global__ void gfinal()
{
    int g = blockIdx.x * blockDim.x + threadIdx.x;
    if (g >= GG) return;
    float cnt  = (float)g_GC[g];
    float norm = fmaxf(cnt, 1.f) * (float)DD;
    float mean = g_GS[g] / norm;
    float var  = fmaxf(g_GQ[g] / norm - mean * mean, 0.f);
    g_MEAN[g] = mean;
    g_RSTD[g] = rsqrtf(var + 1e-5f);
}

__device__ __forceinline__ unsigned fkey(float f)
{
    unsigned u = __float_as_uint(f);
    return (u & 0x80000000u) ? ~u : (u | 0x80000000u);
}
__device__ __forceinline__ float funkey(unsigned u)
{
    return (u & 0x80000000u) ? __uint_as_float(u & 0x7FFFFFFFu) : __uint_as_float(~u);
}

template<bool WRITEH, bool MAXRED>
__global__ void hupdate(const int* __restrict__ batch,
                        const float* __restrict__ gamma, const float* __restrict__ beta)
{
    size_t i = (size_t)blockIdx.x * blockDim.x + threadIdx.x;
    if (i >= NND_C) return;
    int node = (int)(i / DD), c = (int)(i % DD);
    int g = batch[node];
    float v = g_ACC[i] * (1.f / 9.f);
    v = v > 0.f ? v : 0.01f * v;
    float xn = (v - g_MEAN[g]) * g_RSTD[g] * gamma[c] + beta[c];
    float hn = 0.5f * (g_H[i] + xn);
    g_H[i] = hn;
    if (WRITEH) g_HH[i] = __float2half(hn);
    if (MAXRED) atomicMax(&g_OUTU[(size_t)g * DD + c], fkey(hn));
}

__global__ void finalize(float* __restrict__ out)
{
    int i = blockIdx.x * blockDim.x + threadIdx.x;
    if (i < GG * DD) out[i] = funkey(g_OUTU[i]);
}

// ---------------- host orchestration ----------------
extern "C" void kernel_launch(void* const* d_in, const int* in_sizes, int n_in,
                              void* d_out, int out_size)
{
    const float* x     = (const float*)d_in[0];
    const int*   batch = (const int*)d_in[1];
    const int*   EI    = (const int*)d_in[2];
    const float* EA    = (const float*)d_in[3];
    const float* W1    = (const float*)d_in[4];
    const float* b1    = (const float*)d_in[5];
    const float* W2    = (const float*)d_in[6];
    const float* b2    = (const float*)d_in[7];
    const float* Wq    = (const float*)d_in[8];
    const float* bq    = (const float*)d_in[9];
    const float* Wk    = (const float*)d_in[10];
    const float* bk    = (const float*)d_in[11];
    const float* Wv    = (const float*)d_in[12];
    const float* bv    = (const float*)d_in[13];
    const float* We    = (const float*)d_in[14];
    const float* be    = (const float*)d_in[15];
    const float* Ws    = (const float*)d_in[16];
    const float* bs    = (const float*)d_in[17];
    const float* gamma = (const float*)d_in[18];
    const float* beta  = (const float*)d_in[19];
    float* out = (float*)d_out;

    float *pQW, *pACC, *pH, *pXSD, *pGS, *pGQ, *pBSUM, *pBQKV, *pDEN;
    __half *pQKVH, *pHH, *pWNEAH, *pWQKVTH, *pWSUMTH, *pWERTH, *pWQWBH, *pW1TH;
    int *pGC, *pCNT;
    unsigned *pOUTU;
    cudaGetSymbolAddress((void**)&pXSD,     g_XSD);
    cudaGetSymbolAddress((void**)&pQKVH,    g_QKVH);
    cudaGetSymbolAddress((void**)&pQW,      g_QW);
    cudaGetSymbolAddress((void**)&pWNEAH,   g_WNEAH);
    cudaGetSymbolAddress((void**)&pACC,     g_ACC);
    cudaGetSymbolAddress((void**)&pH,       g_H);
    cudaGetSymbolAddress((void**)&pHH,      g_HH);
    cudaGetSymbolAddress((void**)&pGS,      g_GS);
    cudaGetSymbolAddress((void**)&pGQ,      g_GQ);
    cudaGetSymbolAddress((void**)&pGC,      g_GC);
    cudaGetSymbolAddress((void**)&pCNT,     g_CNT);
    cudaGetSymbolAddress((void**)&pBSUM,    g_BSUM);
    cudaGetSymbolAddress((void**)&pBQKV,    g_BQKV);
    cudaGetSymbolAddress((void**)&pDEN,     g_DEN);
    cudaGetSymbolAddress((void**)&pWQKVTH,  g_WQKVTH);
    cudaGetSymbolAddress((void**)&pWSUMTH,  g_WSUMTH);
    cudaGetSymbolAddress((void**)&pWERTH,   g_WERTH);
    cudaGetSymbolAddress((void**)&pWQWBH,   g_WQWBH);
    cudaGetSymbolAddress((void**)&pW1TH,    g_W1TH);
    cudaGetSymbolAddress((void**)&pOUTU,    g_OUTU);

    const int MT = (NN + 127) / 128;        // 391
    const long NND = (long)NN * DD;

    // ---- preprocessing ----
    cudaMemsetAsync(pGC, 0, GG * sizeof(int));
    cudaMemsetAsync(pOUTU, 0, (size_t)GG * DD * sizeof(unsigned));
    count_nodes<<<(NN + 255) / 256, 256>>>(batch);

    trans_qkv_h<<<(NBB * NTT * DD * DD + NBB * NTT * DD + 255) / 256, 256>>>(Wq, Wk, Wv, bq, bk, bv);
    wsumT_h<<<(NBB * DD * DD + NBB * DD + 255) / 256, 256>>>(Ws, bs);
    werT_h<<<(NBB * DD * NTT * EHH + 255) / 256, 256>>>(We);
    wqwb_h<<<(NBB * NTT * 64 * DD + 255) / 256, 256>>>(We);
    w1T_h<<<(64 * DD + 255) / 256, 256>>>(W1);

    cudaMemsetAsync(pCNT, 0, (NN + 1) * sizeof(int));
    csr_count<<<(NE9 + 255) / 256, 256>>>(EI);
    csr_scan<<<1, 1024>>>();
    csr_fill<<<(NE9 + 255) / 256, 256>>>(EI);

    cudaMemcpyAsync(pH, x, NND * sizeof(float), cudaMemcpyDeviceToDevice);
    conv_X<<<(unsigned)((NND + 255) / 256), 256>>>(x);

    // XSD = HH @ [W1src|W1dst]^T
    hgemm<false, true, false><<<dim3(1, MT, 1), 256>>>(
        pHH, pW1TH, nullptr, pXSD, nullptr, NN, DD, 64, 0, 0, 0, 0);
    edge_mlp<<<(NE9 + 7) / 8, 256>>>(EI, EA, W1, b1, W2, b2);

    for (int b = 0; b < NBB; b++) {
        // skip (folded): ACC = HH @ WSUM_b^T + BSUM_b
        hgemm<false, true, false><<<dim3(5, MT, 1), 256>>>(
            pHH, pWSUMTH + (size_t)b * DD * DD, pBSUM + (size_t)b * DD, pACC, nullptr,
            NN, DD, DD, 0, 0, 0, 0);

        // fused Q/K/V (z = 27), fp16 packed output
        hgemm<false, false, true><<<dim3(5, MT, 3 * NTT), 256>>>(
            pHH, pWQKVTH + (size_t)b * 3 * NTT * DD * DD, pBQKV + (size_t)b * 3 * NTT * DD,
            nullptr, pQKVH,
            NN, DD, DD, 0, (long)DD * DD, NND, DD);

        // QW_t = Q_t @ We_t^T (Nout=64, z=9)
        hgemm<false, true, false><<<dim3(1, MT, NTT), 256>>>(
            pQKVH, pWQWBH + (size_t)b * NTT * 64 * DD, nullptr, pQW, nullptr,
            NN, DD, 64, NND, (long)64 * DD, (long)NN * 64, 0);

        cudaMemsetAsync(pDEN, 0, (size_t)NTT * NN * sizeof(float));
        att_pass1<<<(NE9 + 7) / 8, 256>>>();
        att_gather<<<(NN + 7) / 8, 256>>>(be + (size_t)b * NTT * DD);

        // ACC += WNEA @ [stacked We] (K=288)
        hgemm<true, true, false><<<dim3(5, MT, 1), 256>>>(
            pWNEAH, pWERTH + (size_t)b * DD * NTT * EHH, nullptr, pACC, nullptr,
            NN, NTT * EHH, DD, 0, 0, 0, 0);

        cudaMemsetAsync(pGS, 0, GG * sizeof(float));
        cudaMemsetAsync(pGQ, 0, GG * sizeof(float));
        gstats<<<(NN + 7) / 8, 256>>>(batch);
        gfinal<<<1, 256>>>();
        if (b + 1 < NBB)
            hupdate<true, false><<<(unsigned)((NND + 255) / 256), 256>>>(
                batch, gamma + (size_t)b * DD, beta + (size_t)b * DD);
        else
            hupdate<false, true><<<(unsigned)((NND + 255) / 256), 256>>>(
                batch, gamma + (size_t)b * DD, beta + (size_t)b * DD);
    }

    finalize<<<(GG * DD + 255) / 256, 256>>>(out);
}